// round 5
// baseline (speedup 1.0000x reference)
#include <cuda_runtime.h>
#include <math.h>

// ---------------- problem constants ----------------
#define NB    128      // batch
#define WIN   16384
#define DD    4096     // window length (GEMM1 K)
#define HOP   512
#define NRG   25       // NUM_REGIONS
#define NF    1024     // 2*K filters output cols
#define KF    512      // K (spectrogram bins)
#define NW    193      // NR2Y
#define NK2   128      // conv1 out channels
#define D2Y   128      // conv1 kernel width
#define NK3   256      // conv2 out channels
#define D3X   25       // conv2 kernel height
#define KK3   3200     // NK2*D3X (conv2 reduction)
#define NFLAT 49408    // NK3*NW
#define KSPLIT 193
#define KCH   256      // NFLAT / KSPLIT

// ---------------- scratch (device globals: allocation-free) ----------------
__device__ float g_zx[NB*NRG*KF];                       // [b*25+h][512]
__device__ float g_h1[(size_t)NB*D3X*NW*NK2];           // [b][dx][w][k2]
__device__ float g_h2[NB*NK3*NW];                       // [b][k3*193+w]  (post-relu)
__device__ float g_w2t[KK3*NK3];                        // [kk=dx*128+k2][k3]
__device__ float g_part[KSPLIT*NB*NB];                  // [ks][b][m]

// ---------------- K0: transpose conv2 weights ----------------
__global__ __launch_bounds__(256) void k0_w2t(const float* __restrict__ w2)
{
    int kk = blockIdx.x;           // 0..3199, kk = dx*128 + k2
    int k3 = threadIdx.x;          // 0..255
    int k2 = kk & 127, dx = kk >> 7;
    g_w2t[kk*NK3 + k3] = w2[((k3 << 7) + k2)*D3X + dx];
}

// ---------------- K1: spec GEMM + |.|^2 + log epilogue ----------------
// C[3200][1024] = windows(x) @ filters ; zx[3200][512] = log(pair power)
// BM=64, BN=128, BK=16, 256 threads, 4x8 micro-tile
__global__ __launch_bounds__(256) void k1_spec(const float* __restrict__ x,
                                               const float* __restrict__ filt)
{
    __shared__ float As[16][68];    // [k][row], padded
    __shared__ float Bs[16][128];   // [k][n]
    const int tid = threadIdx.x;
    const int m0 = blockIdx.x * 64;
    const int n0 = blockIdx.y * 128;
    const int tr = tid >> 4, tc = tid & 15;

    const int ai  = tid >> 2, ak4 = tid & 3;
    const int arow = m0 + ai;
    const float* aptr = x + (arow/NRG)*WIN + (arow%NRG)*HOP + ak4*4;
    const int bkr = tid >> 5, bn4 = tid & 31;

    float acc[4][8];
    #pragma unroll
    for (int i=0;i<4;i++)
        #pragma unroll
        for (int j=0;j<8;j++) acc[i][j]=0.f;

    for (int k0 = 0; k0 < DD; k0 += 16) {
        float4 av  = *(const float4*)(aptr + k0);
        float4 bv0 = *(const float4*)(filt + (size_t)(k0+bkr  )*NF + n0 + bn4*4);
        float4 bv1 = *(const float4*)(filt + (size_t)(k0+bkr+8)*NF + n0 + bn4*4);
        __syncthreads();
        As[ak4*4+0][ai]=av.x; As[ak4*4+1][ai]=av.y;
        As[ak4*4+2][ai]=av.z; As[ak4*4+3][ai]=av.w;
        *(float4*)&Bs[bkr  ][bn4*4] = bv0;
        *(float4*)&Bs[bkr+8][bn4*4] = bv1;
        __syncthreads();
        #pragma unroll
        for (int k=0;k<16;k++){
            float ra[4];
            #pragma unroll
            for (int i=0;i<4;i++) ra[i] = As[k][tr*4+i];
            float4 b0 = *(const float4*)&Bs[k][tc*8];
            float4 b1 = *(const float4*)&Bs[k][tc*8+4];
            float rb[8] = {b0.x,b0.y,b0.z,b0.w,b1.x,b1.y,b1.z,b1.w};
            #pragma unroll
            for (int i=0;i<4;i++)
                #pragma unroll
                for (int j=0;j<8;j++)
                    acc[i][j] = fmaf(ra[i], rb[j], acc[i][j]);
        }
    }
    // epilogue: adjacent col pairs are (cos, sin) components
    #pragma unroll
    for (int i=0;i<4;i++){
        int row = m0 + tr*4 + i;
        #pragma unroll
        for (int p=0;p<4;p++){
            float c0 = acc[i][2*p], c1 = acc[i][2*p+1];
            g_zx[row*KF + (n0>>1) + tc*4 + p] = logf(fmaf(c0,c0,c1*c1) + 1e-14f);
        }
    }
}

// ---------------- K2: conv1 (1x128 stride 2) + relu ----------------
// per (b,h, k2-half): C[w'=193][k2=64], K=128 over j.  grid (3200, 2)
// h1 layout [b][dx=h][w][k2] -> stores are coalesced float4
__global__ __launch_bounds__(256) void k2_conv1(const float* __restrict__ w1)
{
    __shared__ float zs[KF];            // one zx row
    __shared__ float w1th[D2Y*64];      // [j][k2l]  32KB
    const int tid = threadIdx.x;
    const int bh  = blockIdx.x;
    const int n0h = blockIdx.y * 64;
    const int b = bh / NRG, h = bh % NRG;

    if (tid < 128) *(float4*)&zs[tid*4] = *(const float4*)&g_zx[bh*KF + tid*4];
    #pragma unroll
    for (int it = 0; it < 8; it++) {
        int e4 = tid + it*256;          // 2048 float4s of w1 half
        int j4 = e4 >> 6, k2l = e4 & 63;
        float4 v = *(const float4*)&w1[(n0h + k2l)*D2Y + j4*4];
        w1th[(j4*4+0)*64 + k2l] = v.x;
        w1th[(j4*4+1)*64 + k2l] = v.y;
        w1th[(j4*4+2)*64 + k2l] = v.z;
        w1th[(j4*4+3)*64 + k2l] = v.w;
    }
    __syncthreads();

    const int tr = tid >> 3;   // 0..31 -> 128 w' rows per tile
    const int tc = tid & 7;    // 0..7  -> 64 k2 cols
    float* outb = g_h1 + (size_t)(b*D3X + h)*NW*NK2 + n0h + tc*8;

    for (int w0 = 0; w0 < 256; w0 += 128) {
        float acc[4][8];
        #pragma unroll
        for (int i=0;i<4;i++)
            #pragma unroll
            for (int j=0;j<8;j++) acc[i][j]=0.f;
        int wr[4];
        #pragma unroll
        for (int i=0;i<4;i++){
            int w = w0 + tr*4 + i;
            wr[i] = 2 * (w < NW ? w : (NW-1));   // clamp (invalid rows skipped on store)
        }
        #pragma unroll 4
        for (int j=0;j<D2Y;j++){
            float4 b0 = *(const float4*)&w1th[j*64 + tc*8];
            float4 b1 = *(const float4*)&w1th[j*64 + tc*8 + 4];
            float rb[8] = {b0.x,b0.y,b0.z,b0.w,b1.x,b1.y,b1.z,b1.w};
            float ra[4];
            #pragma unroll
            for (int i=0;i<4;i++) ra[i] = zs[wr[i] + j];
            #pragma unroll
            for (int i=0;i<4;i++)
                #pragma unroll
                for (int jj=0;jj<8;jj++)
                    acc[i][jj] = fmaf(ra[i], rb[jj], acc[i][jj]);
        }
        #pragma unroll
        for (int i=0;i<4;i++){
            int w = w0 + tr*4 + i;
            if (w < NW) {
                float4 o0 = make_float4(fmaxf(acc[i][0],0.f), fmaxf(acc[i][1],0.f),
                                        fmaxf(acc[i][2],0.f), fmaxf(acc[i][3],0.f));
                float4 o1 = make_float4(fmaxf(acc[i][4],0.f), fmaxf(acc[i][5],0.f),
                                        fmaxf(acc[i][6],0.f), fmaxf(acc[i][7],0.f));
                *(float4*)(outb + (size_t)w*NK2)     = o0;
                *(float4*)(outb + (size_t)w*NK2 + 4) = o1;
            }
        }
    }
}

// ---------------- K3: conv2 as GEMM (24704 x 256, K=3200) + relu ----------------
// rows = b*193+w, A[row][kk] = h1[b][dx][w][k2] (kk = dx*128+k2), B = w2t
// BM=64, BN=128, BK=16, grid (386, 2)
__global__ __launch_bounds__(256) void k3_conv2()
{
    __shared__ float As[16][68];
    __shared__ float Bs[16][128];
    const int tid = threadIdx.x;
    const int m0 = blockIdx.x * 64;
    const int n0 = blockIdx.y * 128;
    const int tr = tid >> 4, tc = tid & 15;

    const int ai = tid >> 2, ak4 = tid & 3;
    const int arow = m0 + ai;
    const int ab = arow / NW, aw = arow % NW;
    const float* abase = g_h1 + ((size_t)ab*D3X*NW + aw)*NK2;   // + dx*NW*NK2 + k2
    const int bkr = tid >> 5, bn4 = tid & 31;

    float acc[4][8];
    #pragma unroll
    for (int i=0;i<4;i++)
        #pragma unroll
        for (int j=0;j<8;j++) acc[i][j]=0.f;

    for (int k0 = 0; k0 < KK3; k0 += 16) {
        int dx = k0 >> 7, k2b = k0 & 127;
        float4 av  = *(const float4*)(abase + (size_t)dx*NW*NK2 + k2b + ak4*4);
        float4 bv0 = *(const float4*)(g_w2t + (size_t)(k0+bkr  )*NK3 + n0 + bn4*4);
        float4 bv1 = *(const float4*)(g_w2t + (size_t)(k0+bkr+8)*NK3 + n0 + bn4*4);
        __syncthreads();
        As[ak4*4+0][ai]=av.x; As[ak4*4+1][ai]=av.y;
        As[ak4*4+2][ai]=av.z; As[ak4*4+3][ai]=av.w;
        *(float4*)&Bs[bkr  ][bn4*4] = bv0;
        *(float4*)&Bs[bkr+8][bn4*4] = bv1;
        __syncthreads();
        #pragma unroll
        for (int k=0;k<16;k++){
            float ra[4];
            #pragma unroll
            for (int i=0;i<4;i++) ra[i] = As[k][tr*4+i];
            float4 b0 = *(const float4*)&Bs[k][tc*8];
            float4 b1 = *(const float4*)&Bs[k][tc*8+4];
            float rb[8] = {b0.x,b0.y,b0.z,b0.w,b1.x,b1.y,b1.z,b1.w};
            #pragma unroll
            for (int i=0;i<4;i++)
                #pragma unroll
                for (int j=0;j<8;j++)
                    acc[i][j] = fmaf(ra[i], rb[j], acc[i][j]);
        }
    }
    #pragma unroll
    for (int i=0;i<4;i++){
        int row = m0 + tr*4 + i;
        int b = row / NW, w = row % NW;
        #pragma unroll
        for (int j=0;j<8;j++){
            int k3 = n0 + tc*8 + j;
            g_h2[(size_t)(b*NK3 + k3)*NW + w] = fmaxf(acc[i][j], 0.f);
        }
    }
}

// ---------------- K4: split-K beta matmul partials ----------------
// y[b][m] = sum_i h2flat[b][i] * beta[m][i]; 193 blocks, K-chunk 256 each
__global__ __launch_bounds__(256) void k4_beta(const float* __restrict__ beta)
{
    __shared__ float As[16][132];   // [k][b], padded (132 % 4 == 0: float4-aligned reads)
    __shared__ float Bs[16][132];   // [k][m]
    const int tid = threadIdx.x;
    const int ks = blockIdx.x;
    const int i0base = ks * KCH;
    const int tr = tid >> 4, tc = tid & 15;

    float acc[8][8];
    #pragma unroll
    for (int i=0;i<8;i++)
        #pragma unroll
        for (int j=0;j<8;j++) acc[i][j]=0.f;

    for (int kit = 0; kit < 16; kit++) {
        int i0 = i0base + kit*16;
        float4 av[2], bv[2];
        #pragma unroll
        for (int it=0; it<2; it++){
            int e = tid + it*256;           // 512 float4 loads each side
            int rl = e >> 2, k4 = e & 3;
            av[it] = *(const float4*)(g_h2 + (size_t)rl*NFLAT + i0 + k4*4);
            bv[it] = *(const float4*)(beta + (size_t)rl*NFLAT + i0 + k4*4);
        }
        __syncthreads();
        #pragma unroll
        for (int it=0; it<2; it++){
            int e = tid + it*256;
            int rl = e >> 2, k4 = e & 3;
            As[k4*4+0][rl]=av[it].x; As[k4*4+1][rl]=av[it].y;
            As[k4*4+2][rl]=av[it].z; As[k4*4+3][rl]=av[it].w;
            Bs[k4*4+0][rl]=bv[it].x; Bs[k4*4+1][rl]=bv[it].y;
            Bs[k4*4+2][rl]=bv[it].z; Bs[k4*4+3][rl]=bv[it].w;
        }
        __syncthreads();
        #pragma unroll
        for (int k=0;k<16;k++){
            float4 a0 = *(const float4*)&As[k][tr*8];
            float4 a1 = *(const float4*)&As[k][tr*8+4];
            float4 b0 = *(const float4*)&Bs[k][tc*8];
            float4 b1 = *(const float4*)&Bs[k][tc*8+4];
            float rav[8] = {a0.x,a0.y,a0.z,a0.w,a1.x,a1.y,a1.z,a1.w};
            float rbv[8] = {b0.x,b0.y,b0.z,b0.w,b1.x,b1.y,b1.z,b1.w};
            #pragma unroll
            for (int i=0;i<8;i++)
                #pragma unroll
                for (int j=0;j<8;j++)
                    acc[i][j] = fmaf(rav[i], rbv[j], acc[i][j]);
        }
    }
    float* p = g_part + (size_t)ks*NB*NB;
    #pragma unroll
    for (int i=0;i<8;i++)
        #pragma unroll
        for (int j=0;j<8;j++)
            p[(tr*8+i)*NB + tc*8+j] = acc[i][j];
}

// ---------------- K5: deterministic split-K reduce ----------------
__global__ __launch_bounds__(256) void k5_reduce(float* __restrict__ y)
{
    int o = blockIdx.x*256 + threadIdx.x;   // 16384 outputs
    float s = 0.f;
    #pragma unroll 4
    for (int ks = 0; ks < KSPLIT; ks++)
        s += g_part[(size_t)ks*NB*NB + o];
    y[o] = s;
}

// ---------------- launcher ----------------
extern "C" void kernel_launch(void* const* d_in, const int* in_sizes, int n_in,
                              void* d_out, int out_size)
{
    const float* x    = (const float*)d_in[0];   // 128 x 16384
    const float* filt = (const float*)d_in[1];   // 4096 x 1024
    const float* w1   = (const float*)d_in[2];   // 128 x 128
    const float* w2   = (const float*)d_in[3];   // 256 x 128 x 25
    const float* beta = (const float*)d_in[4];   // 128 x 49408
    float* y = (float*)d_out;                    // 128 x 128

    k0_w2t  <<<KK3, 256>>>(w2);
    k1_spec <<<dim3(50, 8), 256>>>(x, filt);
    k2_conv1<<<dim3(NB*NRG, 2), 256>>>(w1);
    k3_conv2<<<dim3(386, 2), 256>>>();
    k4_beta <<<KSPLIT, 256>>>(beta);
    k5_reduce<<<NB*NB/256, 256>>>(y);
}

// round 6
// speedup vs baseline: 1.6815x; 1.6815x over previous
#include <cuda_runtime.h>
#include <math.h>

// ---------------- problem constants ----------------
#define NB    128      // batch
#define WIN   16384
#define DD    4096     // window length (GEMM1 K)
#define HOP   512
#define NRG   25       // NUM_REGIONS
#define NF    1024     // 2*K filters output cols
#define KF    512      // K (spectrogram bins)
#define NW    193      // NR2Y
#define NK2   128      // conv1 out channels
#define D2Y   128      // conv1 kernel width
#define NK3   256      // conv2 out channels
#define D3X   25       // conv2 kernel height
#define KK3   3200     // NK2*D3X (conv2 reduction)
#define NFLAT 49408    // NK3*NW
#define KSPLIT 193
#define KCH   256      // NFLAT / KSPLIT

typedef unsigned long long ull;

// ---------------- packed f32x2 helpers (sm_103a FFMA2) ----------------
__device__ __forceinline__ ull ffma2(ull a, ull b, ull c) {
    ull d;
    asm("fma.rn.f32x2 %0, %1, %2, %3;" : "=l"(d) : "l"(a), "l"(b), "l"(c));
    return d;
}
__device__ __forceinline__ ull bcast2(float x) {
    ull d; unsigned u = __float_as_uint(x);
    asm("mov.b64 %0, {%1, %1};" : "=l"(d) : "r"(u));
    return d;
}
__device__ __forceinline__ float2 unpk2(ull v) {
    unsigned lo, hi;
    asm("mov.b64 {%0, %1}, %2;" : "=r"(lo), "=r"(hi) : "l"(v));
    return make_float2(__uint_as_float(lo), __uint_as_float(hi));
}

// ---------------- scratch (device globals: allocation-free) ----------------
__device__ float g_zx[NB*NRG*KF];                       // [b*25+h][512]
__device__ float g_h1[(size_t)NB*D3X*NW*NK2];           // [b][dx][w][k2]
__device__ float g_h2[NB*NK3*NW];                       // [b][k3*193+w]  (post-relu)
__device__ float g_w2t[KK3*NK3];                        // [kk=dx*128+k2][k3]
__device__ float g_part[KSPLIT*NB*NB];                  // [ks][b][m]

// ---------------- K0: transpose conv2 weights ----------------
__global__ __launch_bounds__(256) void k0_w2t(const float* __restrict__ w2)
{
    int kk = blockIdx.x;           // 0..3199, kk = dx*128 + k2
    int k3 = threadIdx.x;          // 0..255
    int k2 = kk & 127, dx = kk >> 7;
    g_w2t[kk*NK3 + k3] = w2[((k3 << 7) + k2)*D3X + dx];
}

// ---------------- K1: spec GEMM + |.|^2 + log epilogue ----------------
// C[3200][1024] = windows(x) @ filters ; zx[3200][512] = log(pair power)
// BM=64, BN=128, BK=16, 256 threads, 4x8 micro-tile, FFMA2, double-buffered
__global__ __launch_bounds__(256) void k1_spec(const float* __restrict__ x,
                                               const float* __restrict__ filt)
{
    __shared__ __align__(16) float As[2][16][68];    // [buf][k][row]
    __shared__ __align__(16) float Bs[2][16][128];   // [buf][k][n]
    const int tid = threadIdx.x;
    const int m0 = blockIdx.x * 64;
    const int n0 = blockIdx.y * 128;
    const int tr = tid >> 4, tc = tid & 15;

    const int ai  = tid >> 2, ak4 = tid & 3;
    const int arow = m0 + ai;
    const float* aptr = x + (arow/NRG)*WIN + (arow%NRG)*HOP + ak4*4;
    const int bkr = tid >> 5, bn4 = tid & 31;
    const float* bptr0 = filt + (size_t)bkr*NF + n0 + bn4*4;

    ull acc[4][4];
    #pragma unroll
    for (int i=0;i<4;i++)
        #pragma unroll
        for (int p=0;p<4;p++) acc[i][p]=0ull;

    {   // prologue: tile 0 -> buffer 0
        float4 av  = *(const float4*)(aptr);
        float4 bv0 = *(const float4*)(bptr0);
        float4 bv1 = *(const float4*)(bptr0 + 8*NF);
        As[0][ak4*4+0][ai]=av.x; As[0][ak4*4+1][ai]=av.y;
        As[0][ak4*4+2][ai]=av.z; As[0][ak4*4+3][ai]=av.w;
        *(float4*)&Bs[0][bkr  ][bn4*4] = bv0;
        *(float4*)&Bs[0][bkr+8][bn4*4] = bv1;
        __syncthreads();
    }

    const int NT = DD/16;  // 256
    for (int t = 0; t < NT; t++) {
        const int cur = t & 1;
        float4 nav, nbv0, nbv1;
        if (t+1 < NT) {
            const float* bp = bptr0 + (size_t)(t+1)*16*NF;
            nav  = *(const float4*)(aptr + (t+1)*16);
            nbv0 = *(const float4*)(bp);
            nbv1 = *(const float4*)(bp + 8*NF);
        }
        #pragma unroll
        for (int k=0;k<16;k++){
            ull pa[4];
            #pragma unroll
            for (int i=0;i<4;i++) pa[i] = bcast2(As[cur][k][tr*4+i]);
            ulonglong2 q0 = *(const ulonglong2*)&Bs[cur][k][tc*8];
            ulonglong2 q1 = *(const ulonglong2*)&Bs[cur][k][tc*8+4];
            ull rb[4] = {q0.x, q0.y, q1.x, q1.y};
            #pragma unroll
            for (int i=0;i<4;i++)
                #pragma unroll
                for (int p=0;p<4;p++)
                    acc[i][p] = ffma2(pa[i], rb[p], acc[i][p]);
        }
        if (t+1 < NT) {
            const int nb = cur ^ 1;
            As[nb][ak4*4+0][ai]=nav.x; As[nb][ak4*4+1][ai]=nav.y;
            As[nb][ak4*4+2][ai]=nav.z; As[nb][ak4*4+3][ai]=nav.w;
            *(float4*)&Bs[nb][bkr  ][bn4*4] = nbv0;
            *(float4*)&Bs[nb][bkr+8][bn4*4] = nbv1;
            __syncthreads();
        }
    }
    // epilogue: each packed pair is (cos, sin)
    #pragma unroll
    for (int i=0;i<4;i++){
        int row = m0 + tr*4 + i;
        #pragma unroll
        for (int p=0;p<4;p++){
            float2 cs = unpk2(acc[i][p]);
            g_zx[row*KF + (n0>>1) + tc*4 + p] = logf(fmaf(cs.x,cs.x,cs.y*cs.y) + 1e-14f);
        }
    }
}

// ---------------- K2: conv1 (1x128 stride 2) + relu ----------------
// per (b,h, k2-half): C[w'=193][k2=64], K=128 over j.  grid (3200, 2)
__global__ __launch_bounds__(256) void k2_conv1(const float* __restrict__ w1)
{
    __shared__ __align__(16) float zs[KF];            // one zx row
    __shared__ __align__(16) float w1th[D2Y*64];      // [j][k2l]  32KB
    const int tid = threadIdx.x;
    const int bh  = blockIdx.x;
    const int n0h = blockIdx.y * 64;
    const int b = bh / NRG, h = bh % NRG;

    if (tid < 128) *(float4*)&zs[tid*4] = *(const float4*)&g_zx[bh*KF + tid*4];
    #pragma unroll
    for (int it = 0; it < 8; it++) {
        int e4 = tid + it*256;          // 2048 float4s of w1 half
        int j4 = e4 >> 6, k2l = e4 & 63;
        float4 v = *(const float4*)&w1[(n0h + k2l)*D2Y + j4*4];
        w1th[(j4*4+0)*64 + k2l] = v.x;
        w1th[(j4*4+1)*64 + k2l] = v.y;
        w1th[(j4*4+2)*64 + k2l] = v.z;
        w1th[(j4*4+3)*64 + k2l] = v.w;
    }
    __syncthreads();

    const int tr = tid >> 3;   // 0..31 -> 128 w' rows per tile
    const int tc = tid & 7;    // 0..7  -> 64 k2 cols
    float* outb = g_h1 + (size_t)(b*D3X + h)*NW*NK2 + n0h + tc*8;

    for (int w0 = 0; w0 < 256; w0 += 128) {
        ull acc[4][4];
        #pragma unroll
        for (int i=0;i<4;i++)
            #pragma unroll
            for (int p=0;p<4;p++) acc[i][p]=0ull;
        int wr[4];
        #pragma unroll
        for (int i=0;i<4;i++){
            int w = w0 + tr*4 + i;
            wr[i] = 2 * (w < NW ? w : (NW-1));   // clamp (invalid rows skipped on store)
        }
        #pragma unroll 4
        for (int j=0;j<D2Y;j++){
            ulonglong2 q0 = *(const ulonglong2*)&w1th[j*64 + tc*8];
            ulonglong2 q1 = *(const ulonglong2*)&w1th[j*64 + tc*8 + 4];
            ull rb[4] = {q0.x, q0.y, q1.x, q1.y};
            ull pa[4];
            #pragma unroll
            for (int i=0;i<4;i++) pa[i] = bcast2(zs[wr[i] + j]);
            #pragma unroll
            for (int i=0;i<4;i++)
                #pragma unroll
                for (int p=0;p<4;p++)
                    acc[i][p] = ffma2(pa[i], rb[p], acc[i][p]);
        }
        #pragma unroll
        for (int i=0;i<4;i++){
            int w = w0 + tr*4 + i;
            if (w < NW) {
                float2 v0 = unpk2(acc[i][0]);
                float2 v1 = unpk2(acc[i][1]);
                float2 v2 = unpk2(acc[i][2]);
                float2 v3 = unpk2(acc[i][3]);
                float4 o0 = make_float4(fmaxf(v0.x,0.f), fmaxf(v0.y,0.f),
                                        fmaxf(v1.x,0.f), fmaxf(v1.y,0.f));
                float4 o1 = make_float4(fmaxf(v2.x,0.f), fmaxf(v2.y,0.f),
                                        fmaxf(v3.x,0.f), fmaxf(v3.y,0.f));
                *(float4*)(outb + (size_t)w*NK2)     = o0;
                *(float4*)(outb + (size_t)w*NK2 + 4) = o1;
            }
        }
    }
}

// ---------------- K3: conv2 as GEMM (24704 x 256, K=3200) + relu ----------------
// rows = b*193+w, A[row][kk] = h1[b][dx][w][k2] (kk = dx*128+k2), B = w2t
// BM=64, BN=128, BK=16, grid (386, 2), FFMA2, double-buffered
__global__ __launch_bounds__(256) void k3_conv2()
{
    __shared__ __align__(16) float As[2][16][68];
    __shared__ __align__(16) float Bs[2][16][128];
    const int tid = threadIdx.x;
    const int m0 = blockIdx.x * 64;
    const int n0 = blockIdx.y * 128;
    const int tr = tid >> 4, tc = tid & 15;

    const int ai = tid >> 2, ak4 = tid & 3;
    const int arow = m0 + ai;
    const int ab = arow / NW, aw = arow % NW;
    const float* abase = g_h1 + ((size_t)ab*D3X*NW + aw)*NK2 + ak4*4;  // + dx*NW*NK2 + k2b
    const int bkr = tid >> 5, bn4 = tid & 31;
    const float* bptr0 = g_w2t + (size_t)bkr*NK3 + n0 + bn4*4;

    ull acc[4][4];
    #pragma unroll
    for (int i=0;i<4;i++)
        #pragma unroll
        for (int p=0;p<4;p++) acc[i][p]=0ull;

    {   // prologue: tile 0
        float4 av  = *(const float4*)(abase);
        float4 bv0 = *(const float4*)(bptr0);
        float4 bv1 = *(const float4*)(bptr0 + 8*NK3);
        As[0][ak4*4+0][ai]=av.x; As[0][ak4*4+1][ai]=av.y;
        As[0][ak4*4+2][ai]=av.z; As[0][ak4*4+3][ai]=av.w;
        *(float4*)&Bs[0][bkr  ][bn4*4] = bv0;
        *(float4*)&Bs[0][bkr+8][bn4*4] = bv1;
        __syncthreads();
    }

    const int NT = KK3/16;  // 200
    for (int t = 0; t < NT; t++) {
        const int cur = t & 1;
        float4 nav, nbv0, nbv1;
        if (t+1 < NT) {
            int k0 = (t+1)*16;
            int dx = k0 >> 7, k2b = k0 & 127;
            nav  = *(const float4*)(abase + (size_t)dx*NW*NK2 + k2b);
            const float* bp = bptr0 + (size_t)k0*NK3;
            nbv0 = *(const float4*)(bp);
            nbv1 = *(const float4*)(bp + 8*NK3);
        }
        #pragma unroll
        for (int k=0;k<16;k++){
            ull pa[4];
            #pragma unroll
            for (int i=0;i<4;i++) pa[i] = bcast2(As[cur][k][tr*4+i]);
            ulonglong2 q0 = *(const ulonglong2*)&Bs[cur][k][tc*8];
            ulonglong2 q1 = *(const ulonglong2*)&Bs[cur][k][tc*8+4];
            ull rb[4] = {q0.x, q0.y, q1.x, q1.y};
            #pragma unroll
            for (int i=0;i<4;i++)
                #pragma unroll
                for (int p=0;p<4;p++)
                    acc[i][p] = ffma2(pa[i], rb[p], acc[i][p]);
        }
        if (t+1 < NT) {
            const int nb = cur ^ 1;
            As[nb][ak4*4+0][ai]=nav.x; As[nb][ak4*4+1][ai]=nav.y;
            As[nb][ak4*4+2][ai]=nav.z; As[nb][ak4*4+3][ai]=nav.w;
            *(float4*)&Bs[nb][bkr  ][bn4*4] = nbv0;
            *(float4*)&Bs[nb][bkr+8][bn4*4] = nbv1;
            __syncthreads();
        }
    }
    #pragma unroll
    for (int i=0;i<4;i++){
        int row = m0 + tr*4 + i;
        int b = row / NW, w = row % NW;
        #pragma unroll
        for (int p=0;p<4;p++){
            float2 v = unpk2(acc[i][p]);
            int k3 = n0 + tc*8 + 2*p;
            g_h2[(size_t)(b*NK3 + k3  )*NW + w] = fmaxf(v.x, 0.f);
            g_h2[(size_t)(b*NK3 + k3+1)*NW + w] = fmaxf(v.y, 0.f);
        }
    }
}

// ---------------- K4: split-K beta matmul partials ----------------
// y[b][m] = sum_i h2flat[b][i] * beta[m][i]; 193 blocks, K-chunk 256 each
__global__ __launch_bounds__(256) void k4_beta(const float* __restrict__ beta)
{
    __shared__ __align__(16) float As[16][132];   // [k][b]  (132*4=528 = 33*16, 16B-aligned rows)
    __shared__ __align__(16) float Bs[16][132];   // [k][m]
    const int tid = threadIdx.x;
    const int ks = blockIdx.x;
    const int i0base = ks * KCH;
    const int tr = tid >> 4, tc = tid & 15;

    ull acc[8][4];
    #pragma unroll
    for (int i=0;i<8;i++)
        #pragma unroll
        for (int p=0;p<4;p++) acc[i][p]=0ull;

    for (int kit = 0; kit < 16; kit++) {
        int i0 = i0base + kit*16;
        float4 av[2], bv[2];
        #pragma unroll
        for (int it=0; it<2; it++){
            int e = tid + it*256;           // 512 float4 loads each side
            int rl = e >> 2, k4 = e & 3;
            av[it] = *(const float4*)(g_h2 + (size_t)rl*NFLAT + i0 + k4*4);
            bv[it] = *(const float4*)(beta + (size_t)rl*NFLAT + i0 + k4*4);
        }
        __syncthreads();
        #pragma unroll
        for (int it=0; it<2; it++){
            int e = tid + it*256;
            int rl = e >> 2, k4 = e & 3;
            As[k4*4+0][rl]=av[it].x; As[k4*4+1][rl]=av[it].y;
            As[k4*4+2][rl]=av[it].z; As[k4*4+3][rl]=av[it].w;
            Bs[k4*4+0][rl]=bv[it].x; Bs[k4*4+1][rl]=bv[it].y;
            Bs[k4*4+2][rl]=bv[it].z; Bs[k4*4+3][rl]=bv[it].w;
        }
        __syncthreads();
        #pragma unroll
        for (int k=0;k<16;k++){
            float4 a0 = *(const float4*)&As[k][tr*8];
            float4 a1 = *(const float4*)&As[k][tr*8+4];
            ull pa[8] = {bcast2(a0.x), bcast2(a0.y), bcast2(a0.z), bcast2(a0.w),
                         bcast2(a1.x), bcast2(a1.y), bcast2(a1.z), bcast2(a1.w)};
            ulonglong2 q0 = *(const ulonglong2*)&Bs[k][tc*8];
            ulonglong2 q1 = *(const ulonglong2*)&Bs[k][tc*8+4];
            ull rb[4] = {q0.x, q0.y, q1.x, q1.y};
            #pragma unroll
            for (int i=0;i<8;i++)
                #pragma unroll
                for (int p=0;p<4;p++)
                    acc[i][p] = ffma2(pa[i], rb[p], acc[i][p]);
        }
    }
    float* pp = g_part + (size_t)ks*NB*NB;
    #pragma unroll
    for (int i=0;i<8;i++)
        #pragma unroll
        for (int p=0;p<4;p++){
            float2 v = unpk2(acc[i][p]);
            pp[(tr*8+i)*NB + tc*8 + 2*p    ] = v.x;
            pp[(tr*8+i)*NB + tc*8 + 2*p + 1] = v.y;
        }
}

// ---------------- K5: deterministic split-K reduce ----------------
__global__ __launch_bounds__(256) void k5_reduce(float* __restrict__ y)
{
    int o = blockIdx.x*256 + threadIdx.x;   // 16384 outputs
    float s = 0.f;
    #pragma unroll 4
    for (int ks = 0; ks < KSPLIT; ks++)
        s += g_part[(size_t)ks*NB*NB + o];
    y[o] = s;
}

// ---------------- launcher ----------------
extern "C" void kernel_launch(void* const* d_in, const int* in_sizes, int n_in,
                              void* d_out, int out_size)
{
    const float* x    = (const float*)d_in[0];   // 128 x 16384
    const float* filt = (const float*)d_in[1];   // 4096 x 1024
    const float* w1   = (const float*)d_in[2];   // 128 x 128
    const float* w2   = (const float*)d_in[3];   // 256 x 128 x 25
    const float* beta = (const float*)d_in[4];   // 128 x 49408
    float* y = (float*)d_out;                    // 128 x 128

    k0_w2t  <<<KK3, 256>>>(w2);
    k1_spec <<<dim3(50, 8), 256>>>(x, filt);
    k2_conv1<<<dim3(NB*NRG, 2), 256>>>(w1);
    k3_conv2<<<dim3(386, 2), 256>>>();
    k4_beta <<<KSPLIT, 256>>>(beta);
    k5_reduce<<<NB*NB/256, 256>>>(y);
}

// round 8
// speedup vs baseline: 2.4560x; 1.4606x over previous
#include <cuda_runtime.h>
#include <math.h>

// ---------------- problem constants ----------------
#define NB    128      // batch
#define WIN   16384
#define DD    4096     // window length (GEMM1 K)
#define HOP   512
#define NRG   25       // NUM_REGIONS
#define NF    1024     // 2*K filters output cols
#define KF    512      // K (spectrogram bins)
#define NW    193      // NR2Y
#define NK2   128      // conv1 out channels
#define D2Y   128      // conv1 kernel width
#define NK3   256      // conv2 out channels
#define D3X   25       // conv2 kernel height
#define KK3   3200     // NK2*D3X (conv2 reduction)
#define NFLAT 49408    // NK3*NW
#define KSPLIT 193
#define KCH   256      // NFLAT / KSPLIT

typedef unsigned long long ull;

// ---------------- packed f32x2 helpers (sm_103a FFMA2) ----------------
__device__ __forceinline__ ull ffma2(ull a, ull b, ull c) {
    ull d;
    asm("fma.rn.f32x2 %0, %1, %2, %3;" : "=l"(d) : "l"(a), "l"(b), "l"(c));
    return d;
}
__device__ __forceinline__ ull bcast2(float x) {
    ull d; unsigned u = __float_as_uint(x);
    asm("mov.b64 %0, {%1, %1};" : "=l"(d) : "r"(u));
    return d;
}
__device__ __forceinline__ float2 unpk2(ull v) {
    unsigned lo, hi;
    asm("mov.b64 {%0, %1}, %2;" : "=r"(lo), "=r"(hi) : "l"(v));
    return make_float2(__uint_as_float(lo), __uint_as_float(hi));
}

// ---------------- scratch (device globals: allocation-free) ----------------
__device__ float g_zx[NB*NRG*KF];                       // [b*25+h][512]
__device__ float g_h1[(size_t)NB*D3X*NW*NK2];           // [b][dx][w][k2]
__device__ float g_h2[NB*NK3*NW];                       // [b][k3*193+w]  (post-relu)
__device__ float g_w2t[KK3*NK3];                        // [kk=dx*128+k2][k3]
__device__ float g_part[KSPLIT*NB*NB];                  // [ks][b][m]

// ---------------- K0: transpose conv2 weights ----------------
__global__ __launch_bounds__(256) void k0_w2t(const float* __restrict__ w2)
{
    int kk = blockIdx.x;           // 0..3199, kk = dx*128 + k2
    int k3 = threadIdx.x;          // 0..255
    int k2 = kk & 127, dx = kk >> 7;
    g_w2t[kk*NK3 + k3] = w2[((k3 << 7) + k2)*D3X + dx];
}

// ---------------- K1: spec GEMM + |.|^2 + log epilogue ----------------
// BM=128, BN=128, BK=16, 256 threads, 8x8 micro-tile, FFMA2, double-buffered
__global__ __launch_bounds__(256,2) void k1_spec(const float* __restrict__ x,
                                                 const float* __restrict__ filt)
{
    __shared__ __align__(16) float As[2][16][132];   // [buf][k][row]
    __shared__ __align__(16) float Bs[2][16][132];   // [buf][k][n]
    const int tid = threadIdx.x;
    const int m0 = blockIdx.x * 128;
    const int n0 = blockIdx.y * 128;
    const int tr = tid >> 4, tc = tid & 15;

    const int ai  = tid >> 2, ak4 = tid & 3;
    const int rowA = m0 + ai, rowB = m0 + ai + 64;
    const float* aA = x + (rowA/NRG)*WIN + (rowA%NRG)*HOP + ak4*4;
    const float* aB = x + (rowB/NRG)*WIN + (rowB%NRG)*HOP + ak4*4;
    const int bkr = tid >> 5, bn4 = tid & 31;
    const float* bp0 = filt + (size_t)bkr*NF + n0 + bn4*4;

    ull acc[8][4];
    #pragma unroll
    for (int i=0;i<8;i++)
        #pragma unroll
        for (int p=0;p<4;p++) acc[i][p]=0ull;

    {   // prologue: tile 0 -> buffer 0
        float4 avA = *(const float4*)(aA);
        float4 avB = *(const float4*)(aB);
        float4 bv0 = *(const float4*)(bp0);
        float4 bv1 = *(const float4*)(bp0 + 8*NF);
        As[0][ak4*4+0][ai]=avA.x; As[0][ak4*4+1][ai]=avA.y;
        As[0][ak4*4+2][ai]=avA.z; As[0][ak4*4+3][ai]=avA.w;
        As[0][ak4*4+0][ai+64]=avB.x; As[0][ak4*4+1][ai+64]=avB.y;
        As[0][ak4*4+2][ai+64]=avB.z; As[0][ak4*4+3][ai+64]=avB.w;
        *(float4*)&Bs[0][bkr  ][bn4*4] = bv0;
        *(float4*)&Bs[0][bkr+8][bn4*4] = bv1;
        __syncthreads();
    }

    const int NT = DD/16;  // 256
    for (int t = 0; t < NT; t++) {
        const int cur = t & 1;
        float4 navA, navB, nbv0, nbv1;
        if (t+1 < NT) {
            const float* bp = bp0 + (size_t)(t+1)*16*NF;
            navA = *(const float4*)(aA + (t+1)*16);
            navB = *(const float4*)(aB + (t+1)*16);
            nbv0 = *(const float4*)(bp);
            nbv1 = *(const float4*)(bp + 8*NF);
        }
        #pragma unroll
        for (int k=0;k<16;k++){
            float4 a0 = *(const float4*)&As[cur][k][tr*8];
            float4 a1 = *(const float4*)&As[cur][k][tr*8+4];
            ull pa[8] = {bcast2(a0.x), bcast2(a0.y), bcast2(a0.z), bcast2(a0.w),
                         bcast2(a1.x), bcast2(a1.y), bcast2(a1.z), bcast2(a1.w)};
            ulonglong2 q0 = *(const ulonglong2*)&Bs[cur][k][tc*8];
            ulonglong2 q1 = *(const ulonglong2*)&Bs[cur][k][tc*8+4];
            ull rb[4] = {q0.x, q0.y, q1.x, q1.y};
            #pragma unroll
            for (int i=0;i<8;i++)
                #pragma unroll
                for (int p=0;p<4;p++)
                    acc[i][p] = ffma2(pa[i], rb[p], acc[i][p]);
        }
        if (t+1 < NT) {
            const int nb = cur ^ 1;
            As[nb][ak4*4+0][ai]=navA.x; As[nb][ak4*4+1][ai]=navA.y;
            As[nb][ak4*4+2][ai]=navA.z; As[nb][ak4*4+3][ai]=navA.w;
            As[nb][ak4*4+0][ai+64]=navB.x; As[nb][ak4*4+1][ai+64]=navB.y;
            As[nb][ak4*4+2][ai+64]=navB.z; As[nb][ak4*4+3][ai+64]=navB.w;
            *(float4*)&Bs[nb][bkr  ][bn4*4] = nbv0;
            *(float4*)&Bs[nb][bkr+8][bn4*4] = nbv1;
            __syncthreads();
        }
    }
    // epilogue: each packed pair is (cos, sin)
    #pragma unroll
    for (int i=0;i<8;i++){
        int row = m0 + tr*8 + i;
        #pragma unroll
        for (int p=0;p<4;p++){
            float2 cs = unpk2(acc[i][p]);
            g_zx[row*KF + (n0>>1) + tc*4 + p] = logf(fmaf(cs.x,cs.x,cs.y*cs.y) + 1e-14f);
        }
    }
}

// ---------------- K2: conv1 (1x128 stride 2) + relu, sliding-window ring ----
// grid (3200, 2): block = (b,h) x k2-half.  C[w=0..192][k2=64], K=128 over j.
// even/odd split: A[w][2u]=ze[w+u], A[w][2u+1]=zo[w+u] -> register ring slides.
__global__ __launch_bounds__(256,2) void k2_conv1(const float* __restrict__ w1)
{
    __shared__ __align__(16) float ze[320];           // zs even, padded w/ zeros
    __shared__ __align__(16) float zo[320];           // zs odd
    __shared__ __align__(16) float w1th[D2Y][68];     // [j][k2l] half, padded
    const int tid = threadIdx.x;
    const int bh  = blockIdx.x;
    const int n0h = blockIdx.y * 64;
    const int b = bh / NRG, h = bh % NRG;

    if (tid < 128) {
        float4 v = *(const float4*)&g_zx[bh*KF + tid*4];
        *(float2*)&ze[2*tid] = make_float2(v.x, v.z);
        *(float2*)&zo[2*tid] = make_float2(v.y, v.w);
    } else if (tid < 192) {
        ze[256 + tid-128] = 0.f;
        zo[256 + tid-128] = 0.f;
    }
    #pragma unroll
    for (int it = 0; it < 8; it++) {
        int e = tid + it*256;           // 2048 float4s of w1 half
        int k2l = e >> 5, j4 = e & 31;
        float4 v = *(const float4*)&w1[(n0h + k2l)*D2Y + j4*4];
        w1th[j4*4+0][k2l] = v.x;
        w1th[j4*4+1][k2l] = v.y;
        w1th[j4*4+2][k2l] = v.z;
        w1th[j4*4+3][k2l] = v.w;
    }
    __syncthreads();

    const int tr = tid >> 4;   // 0..15 -> 8-w row groups
    const int tc = tid & 15;   // 0..15 -> 4-k2 col groups
    const int tcK = tc*4;
    float* outb = g_h1 + (size_t)(b*D3X + h)*NW*NK2 + n0h + tcK;

    for (int wt = 0; wt < 2; wt++) {
        const int wbase = wt*128 + tr*8;
        ull acc[8][2];
        #pragma unroll
        for (int i=0;i<8;i++){ acc[i][0]=0ull; acc[i][1]=0ull; }
        ull pe[8], po[8];
        #pragma unroll
        for (int i=0;i<8;i++){ pe[i]=bcast2(ze[wbase+i]); po[i]=bcast2(zo[wbase+i]); }

        // u-step: j=2u uses pe slots (u+i)&7, j=2u+1 uses po; then refill slot u&7
        #define K2_STEP(S) { \
            const int j = 2*(u0+(S)); \
            ulonglong2 qe = *(const ulonglong2*)&w1th[j  ][tcK]; \
            ulonglong2 qo = *(const ulonglong2*)&w1th[j+1][tcK]; \
            _Pragma("unroll") \
            for (int i=0;i<8;i++){ \
                ull a_e = pe[((S)+i)&7], a_o = po[((S)+i)&7]; \
                acc[i][0] = ffma2(a_e, qe.x, acc[i][0]); \
                acc[i][1] = ffma2(a_e, qe.y, acc[i][1]); \
                acc[i][0] = ffma2(a_o, qo.x, acc[i][0]); \
                acc[i][1] = ffma2(a_o, qo.y, acc[i][1]); \
            } \
            pe[(S)&7] = bcast2(ze[wbase + 8 + u0+(S)]); \
            po[(S)&7] = bcast2(zo[wbase + 8 + u0+(S)]); \
        }
        for (int u0 = 0; u0 < 64; u0 += 8) {
            K2_STEP(0) K2_STEP(1) K2_STEP(2) K2_STEP(3)
            K2_STEP(4) K2_STEP(5) K2_STEP(6) K2_STEP(7)
        }
        #undef K2_STEP

        #pragma unroll
        for (int i=0;i<8;i++){
            int w = wbase + i;
            if (w < NW) {
                float2 v0 = unpk2(acc[i][0]);
                float2 v1 = unpk2(acc[i][1]);
                float4 o = make_float4(fmaxf(v0.x,0.f), fmaxf(v0.y,0.f),
                                       fmaxf(v1.x,0.f), fmaxf(v1.y,0.f));
                *(float4*)(outb + (size_t)w*NK2) = o;
            }
        }
    }
}

// ---------------- K3: conv2 as GEMM (24704 x 256, K=3200) + relu ----------------
// BM=128, BN=128, BK=16, grid (193, 2), 8x8 micro-tile, FFMA2, double-buffered
__global__ __launch_bounds__(256,2) void k3_conv2()
{
    __shared__ __align__(16) float As[2][16][132];
    __shared__ __align__(16) float Bs[2][16][132];
    const int tid = threadIdx.x;
    const int m0 = blockIdx.x * 128;
    const int n0 = blockIdx.y * 128;
    const int tr = tid >> 4, tc = tid & 15;

    const int ai = tid >> 2, ak4 = tid & 3;
    const int rowA = m0 + ai, rowB = m0 + ai + 64;
    const float* aA = g_h1 + ((size_t)(rowA/NW)*D3X*NW + (rowA%NW))*NK2 + ak4*4;
    const float* aB = g_h1 + ((size_t)(rowB/NW)*D3X*NW + (rowB%NW))*NK2 + ak4*4;
    const int bkr = tid >> 5, bn4 = tid & 31;
    const float* bp0 = g_w2t + (size_t)bkr*NK3 + n0 + bn4*4;

    ull acc[8][4];
    #pragma unroll
    for (int i=0;i<8;i++)
        #pragma unroll
        for (int p=0;p<4;p++) acc[i][p]=0ull;

    {   // prologue: tile 0 (dx=0, k2b=0)
        float4 avA = *(const float4*)(aA);
        float4 avB = *(const float4*)(aB);
        float4 bv0 = *(const float4*)(bp0);
        float4 bv1 = *(const float4*)(bp0 + 8*NK3);
        As[0][ak4*4+0][ai]=avA.x; As[0][ak4*4+1][ai]=avA.y;
        As[0][ak4*4+2][ai]=avA.z; As[0][ak4*4+3][ai]=avA.w;
        As[0][ak4*4+0][ai+64]=avB.x; As[0][ak4*4+1][ai+64]=avB.y;
        As[0][ak4*4+2][ai+64]=avB.z; As[0][ak4*4+3][ai+64]=avB.w;
        *(float4*)&Bs[0][bkr  ][bn4*4] = bv0;
        *(float4*)&Bs[0][bkr+8][bn4*4] = bv1;
        __syncthreads();
    }

    const int NT = KK3/16;  // 200
    for (int t = 0; t < NT; t++) {
        const int cur = t & 1;
        float4 navA, navB, nbv0, nbv1;
        if (t+1 < NT) {
            int k0 = (t+1)*16;
            int dx = k0 >> 7, k2b = k0 & 127;
            size_t aoff = (size_t)dx*NW*NK2 + k2b;
            navA = *(const float4*)(aA + aoff);
            navB = *(const float4*)(aB + aoff);
            const float* bp = bp0 + (size_t)k0*NK3;
            nbv0 = *(const float4*)(bp);
            nbv1 = *(const float4*)(bp + 8*NK3);
        }
        #pragma unroll
        for (int k=0;k<16;k++){
            float4 a0 = *(const float4*)&As[cur][k][tr*8];
            float4 a1 = *(const float4*)&As[cur][k][tr*8+4];
            ull pa[8] = {bcast2(a0.x), bcast2(a0.y), bcast2(a0.z), bcast2(a0.w),
                         bcast2(a1.x), bcast2(a1.y), bcast2(a1.z), bcast2(a1.w)};
            ulonglong2 q0 = *(const ulonglong2*)&Bs[cur][k][tc*8];
            ulonglong2 q1 = *(const ulonglong2*)&Bs[cur][k][tc*8+4];
            ull rb[4] = {q0.x, q0.y, q1.x, q1.y};
            #pragma unroll
            for (int i=0;i<8;i++)
                #pragma unroll
                for (int p=0;p<4;p++)
                    acc[i][p] = ffma2(pa[i], rb[p], acc[i][p]);
        }
        if (t+1 < NT) {
            const int nb = cur ^ 1;
            As[nb][ak4*4+0][ai]=navA.x; As[nb][ak4*4+1][ai]=navA.y;
            As[nb][ak4*4+2][ai]=navA.z; As[nb][ak4*4+3][ai]=navA.w;
            As[nb][ak4*4+0][ai+64]=navB.x; As[nb][ak4*4+1][ai+64]=navB.y;
            As[nb][ak4*4+2][ai+64]=navB.z; As[nb][ak4*4+3][ai+64]=navB.w;
            *(float4*)&Bs[nb][bkr  ][bn4*4] = nbv0;
            *(float4*)&Bs[nb][bkr+8][bn4*4] = nbv1;
            __syncthreads();
        }
    }
    #pragma unroll
    for (int i=0;i<8;i++){
        int row = m0 + tr*8 + i;
        int b = row / NW, w = row % NW;
        #pragma unroll
        for (int p=0;p<4;p++){
            float2 v = unpk2(acc[i][p]);
            int k3 = n0 + tc*8 + 2*p;
            g_h2[(size_t)(b*NK3 + k3  )*NW + w] = fmaxf(v.x, 0.f);
            g_h2[(size_t)(b*NK3 + k3+1)*NW + w] = fmaxf(v.y, 0.f);
        }
    }
}

// ---------------- K4: split-K beta matmul partials ----------------
__global__ __launch_bounds__(256) void k4_beta(const float* __restrict__ beta)
{
    __shared__ __align__(16) float As[16][132];   // [k][b]
    __shared__ __align__(16) float Bs[16][132];   // [k][m]
    const int tid = threadIdx.x;
    const int ks = blockIdx.x;
    const int i0base = ks * KCH;
    const int tr = tid >> 4, tc = tid & 15;

    ull acc[8][4];
    #pragma unroll
    for (int i=0;i<8;i++)
        #pragma unroll
        for (int p=0;p<4;p++) acc[i][p]=0ull;

    for (int kit = 0; kit < 16; kit++) {
        int i0 = i0base + kit*16;
        float4 av[2], bv[2];
        #pragma unroll
        for (int it=0; it<2; it++){
            int e = tid + it*256;
            int rl = e >> 2, k4 = e & 3;
            av[it] = *(const float4*)(g_h2 + (size_t)rl*NFLAT + i0 + k4*4);
            bv[it] = *(const float4*)(beta + (size_t)rl*NFLAT + i0 + k4*4);
        }
        __syncthreads();
        #pragma unroll
        for (int it=0; it<2; it++){
            int e = tid + it*256;
            int rl = e >> 2, k4 = e & 3;
            As[k4*4+0][rl]=av[it].x; As[k4*4+1][rl]=av[it].y;
            As[k4*4+2][rl]=av[it].z; As[k4*4+3][rl]=av[it].w;
            Bs[k4*4+0][rl]=bv[it].x; Bs[k4*4+1][rl]=bv[it].y;
            Bs[k4*4+2][rl]=bv[it].z; Bs[k4*4+3][rl]=bv[it].w;
        }
        __syncthreads();
        #pragma unroll
        for (int k=0;k<16;k++){
            float4 a0 = *(const float4*)&As[k][tr*8];
            float4 a1 = *(const float4*)&As[k][tr*8+4];
            ull pa[8] = {bcast2(a0.x), bcast2(a0.y), bcast2(a0.z), bcast2(a0.w),
                         bcast2(a1.x), bcast2(a1.y), bcast2(a1.z), bcast2(a1.w)};
            ulonglong2 q0 = *(const ulonglong2*)&Bs[k][tc*8];
            ulonglong2 q1 = *(const ulonglong2*)&Bs[k][tc*8+4];
            ull rb[4] = {q0.x, q0.y, q1.x, q1.y};
            #pragma unroll
            for (int i=0;i<8;i++)
                #pragma unroll
                for (int p=0;p<4;p++)
                    acc[i][p] = ffma2(pa[i], rb[p], acc[i][p]);
        }
    }
    float* pp = g_part + (size_t)ks*NB*NB;
    #pragma unroll
    for (int i=0;i<8;i++)
        #pragma unroll
        for (int p=0;p<4;p++){
            float2 v = unpk2(acc[i][p]);
            pp[(tr*8+i)*NB + tc*8 + 2*p    ] = v.x;
            pp[(tr*8+i)*NB + tc*8 + 2*p + 1] = v.y;
        }
}

// ---------------- K5: deterministic split-K reduce ----------------
__global__ __launch_bounds__(256) void k5_reduce(float* __restrict__ y)
{
    int o = blockIdx.x*256 + threadIdx.x;   // 16384 outputs
    float s = 0.f;
    #pragma unroll 4
    for (int ks = 0; ks < KSPLIT; ks++)
        s += g_part[(size_t)ks*NB*NB + o];
    y[o] = s;
}

// ---------------- launcher ----------------
extern "C" void kernel_launch(void* const* d_in, const int* in_sizes, int n_in,
                              void* d_out, int out_size)
{
    const float* x    = (const float*)d_in[0];   // 128 x 16384
    const float* filt = (const float*)d_in[1];   // 4096 x 1024
    const float* w1   = (const float*)d_in[2];   // 128 x 128
    const float* w2   = (const float*)d_in[3];   // 256 x 128 x 25
    const float* beta = (const float*)d_in[4];   // 128 x 49408
    float* y = (float*)d_out;                    // 128 x 128

    k0_w2t  <<<KK3, 256>>>(w2);
    k1_spec <<<dim3(25, 8), 256>>>(x, filt);
    k2_conv1<<<dim3(NB*NRG, 2), 256>>>(w1);
    k3_conv2<<<dim3(193, 2), 256>>>();
    k4_beta <<<KSPLIT, 256>>>(beta);
    k5_reduce<<<NB*NB/256, 256>>>(y);
}

// round 12
// speedup vs baseline: 3.1408x; 1.2788x over previous
#include <cuda_runtime.h>
#include <cuda_bf16.h>
#include <cstdint>
#include <math.h>

// ---------------- problem constants ----------------
#define NB    128      // batch
#define WIN   16384
#define DD    4096     // window length (GEMM1 K)
#define HOP   512
#define NRG   25       // NUM_REGIONS
#define NF    1024     // 2*K filters output cols
#define KF    512      // K (spectrogram bins)
#define NW    193      // NR2Y
#define NK2   128      // conv1 out channels
#define D2Y   128      // conv1 kernel width
#define NK3   256      // conv2 out channels
#define D3X   25       // conv2 kernel height
#define KK3   3200     // NK2*D3X (conv2 reduction)
#define NFLAT 49408    // NK3*NW
#define KSPLIT 193
#define KCH   256      // NFLAT / KSPLIT

typedef unsigned long long ull;

// ---------------- packed f32x2 helpers (sm_103a FFMA2) ----------------
__device__ __forceinline__ ull ffma2(ull a, ull b, ull c) {
    ull d;
    asm("fma.rn.f32x2 %0, %1, %2, %3;" : "=l"(d) : "l"(a), "l"(b), "l"(c));
    return d;
}
__device__ __forceinline__ ull bcast2(float x) {
    ull d; unsigned u = __float_as_uint(x);
    asm("mov.b64 %0, {%1, %1};" : "=l"(d) : "r"(u));
    return d;
}
__device__ __forceinline__ float2 unpk2(ull v) {
    unsigned lo, hi;
    asm("mov.b64 {%0, %1}, %2;" : "=r"(lo), "=r"(hi) : "l"(v));
    return make_float2(__uint_as_float(lo), __uint_as_float(hi));
}

// ---------------- bf16 split helper ----------------
__device__ __forceinline__ void bf16split(float r, unsigned short &h, unsigned short &l) {
    __nv_bfloat16 bh = __float2bfloat16(r);
    float lo = r - __bfloat162float(bh);
    h = __bfloat16_as_ushort(bh);
    l = __bfloat16_as_ushort(__float2bfloat16(lo));
}

// ---------------- mma.sync bf16 (sm_80+ baseline; works at compute_103) ----
__device__ __forceinline__ void mma16816(float* c, const unsigned* a, unsigned b0, unsigned b1) {
    asm volatile(
        "mma.sync.aligned.m16n8k16.row.col.f32.bf16.bf16.f32 "
        "{%0,%1,%2,%3}, {%4,%5,%6,%7}, {%8,%9}, {%0,%1,%2,%3};"
        : "+f"(c[0]), "+f"(c[1]), "+f"(c[2]), "+f"(c[3])
        : "r"(a[0]), "r"(a[1]), "r"(a[2]), "r"(a[3]), "r"(b0), "r"(b1));
}

// ---------------- scratch (device globals: allocation-free) ----------------
__device__ float g_zx[NB*NRG*KF];                         // [b*25+h][512]
__device__ unsigned short g_h1h[(size_t)NB*D3X*NW*NK2];   // bf16 hi [b][dx][w][k2]
__device__ unsigned short g_h1l[(size_t)NB*D3X*NW*NK2];   // bf16 lo
__device__ unsigned short g_w2h[(size_t)NK3*KK3];         // bf16 hi [k3][kk]
__device__ unsigned short g_w2l[(size_t)NK3*KK3];         // bf16 lo
__device__ float g_h2[NB*NK3*NW];                         // [b][k3*193+w]  (post-relu)
__device__ float g_part[KSPLIT*NB*NB];                    // [ks][b][m]

// ---------------- K0: w2 -> bf16 hi/lo, [k3][kk=dx*128+k2] K-major ----------
__global__ __launch_bounds__(256) void k0_w2b(const float* __restrict__ w2)
{
    int k3 = blockIdx.x;           // 0..255
    for (int kk = threadIdx.x; kk < KK3; kk += 256) {
        float v = w2[((k3 << 7) + (kk & 127))*D3X + (kk >> 7)];
        unsigned short h, l; bf16split(v, h, l);
        g_w2h[(size_t)k3*KK3 + kk] = h;
        g_w2l[(size_t)k3*KK3 + kk] = l;
    }
}

// ---------------- K1: spec GEMM + |.|^2 + log epilogue (FFMA2) -------------
__global__ __launch_bounds__(256,2) void k1_spec(const float* __restrict__ x,
                                                 const float* __restrict__ filt)
{
    __shared__ __align__(16) float As[2][16][132];   // [buf][k][row]
    __shared__ __align__(16) float Bs[2][16][132];   // [buf][k][n]
    const int tid = threadIdx.x;
    const int m0 = blockIdx.x * 128;
    const int n0 = blockIdx.y * 128;
    const int tr = tid >> 4, tc = tid & 15;

    const int ai  = tid >> 2, ak4 = tid & 3;
    const int rowA = m0 + ai, rowB = m0 + ai + 64;
    const float* aA = x + (rowA/NRG)*WIN + (rowA%NRG)*HOP + ak4*4;
    const float* aB = x + (rowB/NRG)*WIN + (rowB%NRG)*HOP + ak4*4;
    const int bkr = tid >> 5, bn4 = tid & 31;
    const float* bp0 = filt + (size_t)bkr*NF + n0 + bn4*4;

    ull acc[8][4];
    #pragma unroll
    for (int i=0;i<8;i++)
        #pragma unroll
        for (int p=0;p<4;p++) acc[i][p]=0ull;

    {
        float4 avA = *(const float4*)(aA);
        float4 avB = *(const float4*)(aB);
        float4 bv0 = *(const float4*)(bp0);
        float4 bv1 = *(const float4*)(bp0 + 8*NF);
        As[0][ak4*4+0][ai]=avA.x; As[0][ak4*4+1][ai]=avA.y;
        As[0][ak4*4+2][ai]=avA.z; As[0][ak4*4+3][ai]=avA.w;
        As[0][ak4*4+0][ai+64]=avB.x; As[0][ak4*4+1][ai+64]=avB.y;
        As[0][ak4*4+2][ai+64]=avB.z; As[0][ak4*4+3][ai+64]=avB.w;
        *(float4*)&Bs[0][bkr  ][bn4*4] = bv0;
        *(float4*)&Bs[0][bkr+8][bn4*4] = bv1;
        __syncthreads();
    }

    const int NT = DD/16;  // 256
    for (int t = 0; t < NT; t++) {
        const int cur = t & 1;
        float4 navA, navB, nbv0, nbv1;
        if (t+1 < NT) {
            const float* bp = bp0 + (size_t)(t+1)*16*NF;
            navA = *(const float4*)(aA + (t+1)*16);
            navB = *(const float4*)(aB + (t+1)*16);
            nbv0 = *(const float4*)(bp);
            nbv1 = *(const float4*)(bp + 8*NF);
        }
        #pragma unroll
        for (int k=0;k<16;k++){
            float4 a0 = *(const float4*)&As[cur][k][tr*8];
            float4 a1 = *(const float4*)&As[cur][k][tr*8+4];
            ull pa[8] = {bcast2(a0.x), bcast2(a0.y), bcast2(a0.z), bcast2(a0.w),
                         bcast2(a1.x), bcast2(a1.y), bcast2(a1.z), bcast2(a1.w)};
            ulonglong2 q0 = *(const ulonglong2*)&Bs[cur][k][tc*8];
            ulonglong2 q1 = *(const ulonglong2*)&Bs[cur][k][tc*8+4];
            ull rb[4] = {q0.x, q0.y, q1.x, q1.y};
            #pragma unroll
            for (int i=0;i<8;i++)
                #pragma unroll
                for (int p=0;p<4;p++)
                    acc[i][p] = ffma2(pa[i], rb[p], acc[i][p]);
        }
        if (t+1 < NT) {
            const int nb = cur ^ 1;
            As[nb][ak4*4+0][ai]=navA.x; As[nb][ak4*4+1][ai]=navA.y;
            As[nb][ak4*4+2][ai]=navA.z; As[nb][ak4*4+3][ai]=navA.w;
            As[nb][ak4*4+0][ai+64]=navB.x; As[nb][ak4*4+1][ai+64]=navB.y;
            As[nb][ak4*4+2][ai+64]=navB.z; As[nb][ak4*4+3][ai+64]=navB.w;
            *(float4*)&Bs[nb][bkr  ][bn4*4] = nbv0;
            *(float4*)&Bs[nb][bkr+8][bn4*4] = nbv1;
            __syncthreads();
        }
    }
    #pragma unroll
    for (int i=0;i<8;i++){
        int row = m0 + tr*8 + i;
        #pragma unroll
        for (int p=0;p<4;p++){
            float2 cs = unpk2(acc[i][p]);
            g_zx[row*KF + (n0>>1) + tc*4 + p] = logf(fmaf(cs.x,cs.x,cs.y*cs.y) + 1e-14f);
        }
    }
}

// ---------------- K2: conv1 (1x128 stride 2) + relu -> bf16 hi/lo h1 -------
__global__ __launch_bounds__(256,2) void k2_conv1(const float* __restrict__ w1)
{
    __shared__ __align__(16) float ze[320];
    __shared__ __align__(16) float zo[320];
    __shared__ __align__(16) float w1th[D2Y][68];
    const int tid = threadIdx.x;
    const int bh  = blockIdx.x;
    const int n0h = blockIdx.y * 64;
    const int b = bh / NRG, h = bh % NRG;

    if (tid < 128) {
        float4 v = *(const float4*)&g_zx[bh*KF + tid*4];
        *(float2*)&ze[2*tid] = make_float2(v.x, v.z);
        *(float2*)&zo[2*tid] = make_float2(v.y, v.w);
    } else if (tid < 192) {
        ze[256 + tid-128] = 0.f;
        zo[256 + tid-128] = 0.f;
    }
    #pragma unroll
    for (int it = 0; it < 8; it++) {
        int e = tid + it*256;
        int k2l = e >> 5, j4 = e & 31;
        float4 v = *(const float4*)&w1[(n0h + k2l)*D2Y + j4*4];
        w1th[j4*4+0][k2l] = v.x;
        w1th[j4*4+1][k2l] = v.y;
        w1th[j4*4+2][k2l] = v.z;
        w1th[j4*4+3][k2l] = v.w;
    }
    __syncthreads();

    const int tr = tid >> 4;
    const int tc = tid & 15;
    const int tcK = tc*4;
    const size_t Ebase = (size_t)(b*D3X + h)*NW*NK2 + n0h + tcK;

    for (int wt = 0; wt < 2; wt++) {
        const int wbase = wt*128 + tr*8;
        ull acc[8][2];
        #pragma unroll
        for (int i=0;i<8;i++){ acc[i][0]=0ull; acc[i][1]=0ull; }
        ull pe[8], po[8];
        #pragma unroll
        for (int i=0;i<8;i++){ pe[i]=bcast2(ze[wbase+i]); po[i]=bcast2(zo[wbase+i]); }

        #define K2_STEP(S) { \
            const int j = 2*(u0+(S)); \
            ulonglong2 qe = *(const ulonglong2*)&w1th[j  ][tcK]; \
            ulonglong2 qo = *(const ulonglong2*)&w1th[j+1][tcK]; \
            _Pragma("unroll") \
            for (int i=0;i<8;i++){ \
                ull a_e = pe[((S)+i)&7], a_o = po[((S)+i)&7]; \
                acc[i][0] = ffma2(a_e, qe.x, acc[i][0]); \
                acc[i][1] = ffma2(a_e, qe.y, acc[i][1]); \
                acc[i][0] = ffma2(a_o, qo.x, acc[i][0]); \
                acc[i][1] = ffma2(a_o, qo.y, acc[i][1]); \
            } \
            pe[(S)&7] = bcast2(ze[wbase + 8 + u0+(S)]); \
            po[(S)&7] = bcast2(zo[wbase + 8 + u0+(S)]); \
        }
        for (int u0 = 0; u0 < 64; u0 += 8) {
            K2_STEP(0) K2_STEP(1) K2_STEP(2) K2_STEP(3)
            K2_STEP(4) K2_STEP(5) K2_STEP(6) K2_STEP(7)
        }
        #undef K2_STEP

        #pragma unroll
        for (int i=0;i<8;i++){
            int w = wbase + i;
            if (w < NW) {
                float2 v0 = unpk2(acc[i][0]);
                float2 v1 = unpk2(acc[i][1]);
                float r[4] = {fmaxf(v0.x,0.f), fmaxf(v0.y,0.f),
                              fmaxf(v1.x,0.f), fmaxf(v1.y,0.f)};
                unsigned short hh[4], ll[4];
                #pragma unroll
                for (int j=0;j<4;j++) bf16split(r[j], hh[j], ll[j]);
                ull ph = (ull)hh[0] | ((ull)hh[1]<<16) | ((ull)hh[2]<<32) | ((ull)hh[3]<<48);
                ull pl = (ull)ll[0] | ((ull)ll[1]<<16) | ((ull)ll[2]<<32) | ((ull)ll[3]<<48);
                size_t E = Ebase + (size_t)w*NK2;
                *(ull*)(g_h1h + E) = ph;
                *(ull*)(g_h1l + E) = pl;
            }
        }
    }
}

// ---------------- K3: conv2 GEMM via mma.sync bf16-split + relu ------------
// grid (193, 2): CTA tile 128x128, warp tile 64x32 (2x4 warps), K-chunks of 64.
// smem: A/B hi+lo, [128][72] bf16 each (stride 72 -> conflict-free frag LDS).
#define K3_SA     72                         // padded row stride (bf16)
#define K3_TILE_B (128*K3_SA*2)              // 18432 bytes per tile
#define K3_SMEM_TOTAL (4*K3_TILE_B)          // 73728 bytes

__global__ __launch_bounds__(256) void k3_conv2_mma()
{
    extern __shared__ char smem[];
    unsigned short* sAh = (unsigned short*)(smem);
    unsigned short* sAl = (unsigned short*)(smem + K3_TILE_B);
    unsigned short* sBh = (unsigned short*)(smem + 2*K3_TILE_B);
    unsigned short* sBl = (unsigned short*)(smem + 3*K3_TILE_B);
    const unsigned* uAh = (const unsigned*)sAh;
    const unsigned* uAl = (const unsigned*)sAl;
    const unsigned* uBh = (const unsigned*)sBh;
    const unsigned* uBl = (const unsigned*)sBl;

    const int tid = threadIdx.x;
    const int wid = tid >> 5, lane = tid & 31;
    const int g = lane >> 2, tg = lane & 3;
    const int wm = wid >> 2, wn = wid & 3;       // 2 x 4 warp grid
    const int m0 = blockIdx.x * 128;
    const int n0 = blockIdx.y * 128;

    // ---- load geometry: A rows, 4 uint4 per thread per tile ----
    size_t aoff[4]; int asm_[4];
    #pragma unroll
    for (int i=0;i<4;i++){
        int e = tid + i*256;           // 1024 uint4 of A tile
        int row = e >> 3, c8 = e & 7;  // 8 bf16 per uint4
        int m = m0 + row;
        int b = m / NW, w = m % NW;
        aoff[i] = (size_t)b*617600 + (size_t)w*128 + c8*8;   // + dx*24704 + k2b
        asm_[i] = row*9 + c8;          // uint4 index (72 bf16 = 9 uint4 per row)
    }
    size_t boff[4]; int bsm[4];
    #pragma unroll
    for (int i=0;i<4;i++){
        int e = tid + i*256;
        int n = e >> 3, c8 = e & 7;
        boff[i] = (size_t)(n0 + n)*KK3 + c8*8;               // + t*64
        bsm[i] = n*9 + c8;
    }

    float acc[4][4][4];    // [mt][nt][frag]
    #pragma unroll
    for (int mt=0;mt<4;mt++)
        #pragma unroll
        for (int nt=0;nt<4;nt++)
            #pragma unroll
            for (int q=0;q<4;q++) acc[mt][nt][q]=0.f;

    // fragment base indices in uint units (2 bf16)
    const int aRowBase = wm*64 + g;    // + mt*16 (+8)
    const int bRowBase = wn*32 + g;    // + nt*8

    for (int t = 0; t < 50; t++) {
        const int dx = t >> 1, k2b = (t & 1) * 64;
        const size_t ao = (size_t)dx*24704 + k2b;
        const size_t bo = (size_t)t*64;

        uint4 rah[4], ral[4], rbh[4], rbl[4];
        #pragma unroll
        for (int i=0;i<4;i++){
            rah[i] = *(const uint4*)(g_h1h + aoff[i] + ao);
            ral[i] = *(const uint4*)(g_h1l + aoff[i] + ao);
            rbh[i] = *(const uint4*)(g_w2h + boff[i] + bo);
            rbl[i] = *(const uint4*)(g_w2l + boff[i] + bo);
        }
        __syncthreads();   // previous chunk's frag reads complete
        #pragma unroll
        for (int i=0;i<4;i++){
            ((uint4*)sAh)[asm_[i]] = rah[i];
            ((uint4*)sAl)[asm_[i]] = ral[i];
            ((uint4*)sBh)[bsm[i]] = rbh[i];
            ((uint4*)sBl)[bsm[i]] = rbl[i];
        }
        __syncthreads();

        #pragma unroll
        for (int kt=0;kt<4;kt++){
            const int kc = kt*8 + tg;   // uint col within chunk
            // B fragments for all 4 n-tiles (hi & lo)
            unsigned bh0[4], bh1[4], bl0[4], bl1[4];
            #pragma unroll
            for (int nt=0;nt<4;nt++){
                int bi = (bRowBase + nt*8)*36 + kc;
                bh0[nt] = uBh[bi];     bh1[nt] = uBh[bi + 4];
                bl0[nt] = uBl[bi];     bl1[nt] = uBl[bi + 4];
            }
            #pragma unroll
            for (int mt=0;mt<4;mt++){
                int ai0 = (aRowBase + mt*16)*36 + kc;
                int ai1 = ai0 + 8*36;
                unsigned ah[4] = {uAh[ai0], uAh[ai1], uAh[ai0+4], uAh[ai1+4]};
                unsigned al[4] = {uAl[ai0], uAl[ai1], uAl[ai0+4], uAl[ai1+4]};
                #pragma unroll
                for (int nt=0;nt<4;nt++){
                    mma16816(acc[mt][nt], ah, bh0[nt], bh1[nt]);
                    mma16816(acc[mt][nt], ah, bl0[nt], bl1[nt]);
                    mma16816(acc[mt][nt], al, bh0[nt], bh1[nt]);
                }
            }
        }
    }

    // epilogue: relu + store to g_h2[(b*256+k3)*193 + w]
    #pragma unroll
    for (int mt=0;mt<4;mt++){
        int m_lo = m0 + wm*64 + mt*16 + g;
        int b_lo = m_lo / NW, w_lo = m_lo % NW;
        int m_hi = m_lo + 8;
        int b_hi = m_hi / NW, w_hi = m_hi % NW;
        #pragma unroll
        for (int nt=0;nt<4;nt++){
            int k3 = n0 + wn*32 + nt*8 + tg*2;
            g_h2[(size_t)(b_lo*NK3 + k3  )*NW + w_lo] = fmaxf(acc[mt][nt][0], 0.f);
            g_h2[(size_t)(b_lo*NK3 + k3+1)*NW + w_lo] = fmaxf(acc[mt][nt][1], 0.f);
            g_h2[(size_t)(b_hi*NK3 + k3  )*NW + w_hi] = fmaxf(acc[mt][nt][2], 0.f);
            g_h2[(size_t)(b_hi*NK3 + k3+1)*NW + w_hi] = fmaxf(acc[mt][nt][3], 0.f);
        }
    }
}

// ---------------- K4: split-K beta matmul partials ----------------
__global__ __launch_bounds__(256) void k4_beta(const float* __restrict__ beta)
{
    __shared__ __align__(16) float As[16][132];   // [k][b]
    __shared__ __align__(16) float Bs[16][132];   // [k][m]
    const int tid = threadIdx.x;
    const int ks = blockIdx.x;
    const int i0base = ks * KCH;
    const int tr = tid >> 4, tc = tid & 15;

    ull acc[8][4];
    #pragma unroll
    for (int i=0;i<8;i++)
        #pragma unroll
        for (int p=0;p<4;p++) acc[i][p]=0ull;

    for (int kit = 0; kit < 16; kit++) {
        int i0 = i0base + kit*16;
        float4 av[2], bv[2];
        #pragma unroll
        for (int it=0; it<2; it++){
            int e = tid + it*256;
            int rl = e >> 2, k4 = e & 3;
            av[it] = *(const float4*)(g_h2 + (size_t)rl*NFLAT + i0 + k4*4);
            bv[it] = *(const float4*)(beta + (size_t)rl*NFLAT + i0 + k4*4);
        }
        __syncthreads();
        #pragma unroll
        for (int it=0; it<2; it++){
            int e = tid + it*256;
            int rl = e >> 2, k4 = e & 3;
            As[k4*4+0][rl]=av[it].x; As[k4*4+1][rl]=av[it].y;
            As[k4*4+2][rl]=av[it].z; As[k4*4+3][rl]=av[it].w;
            Bs[k4*4+0][rl]=bv[it].x; Bs[k4*4+1][rl]=bv[it].y;
            Bs[k4*4+2][rl]=bv[it].z; Bs[k4*4+3][rl]=bv[it].w;
        }
        __syncthreads();
        #pragma unroll
        for (int k=0;k<16;k++){
            float4 a0 = *(const float4*)&As[k][tr*8];
            float4 a1 = *(const float4*)&As[k][tr*8+4];
            ull pa[8] = {bcast2(a0.x), bcast2(a0.y), bcast2(a0.z), bcast2(a0.w),
                         bcast2(a1.x), bcast2(a1.y), bcast2(a1.z), bcast2(a1.w)};
            ulonglong2 q0 = *(const ulonglong2*)&Bs[k][tc*8];
            ulonglong2 q1 = *(const ulonglong2*)&Bs[k][tc*8+4];
            ull rb[4] = {q0.x, q0.y, q1.x, q1.y};
            #pragma unroll
            for (int i=0;i<8;i++)
                #pragma unroll
                for (int p=0;p<4;p++)
                    acc[i][p] = ffma2(pa[i], rb[p], acc[i][p]);
        }
    }
    float* pp = g_part + (size_t)ks*NB*NB;
    #pragma unroll
    for (int i=0;i<8;i++)
        #pragma unroll
        for (int p=0;p<4;p++){
            float2 v = unpk2(acc[i][p]);
            pp[(tr*8+i)*NB + tc*8 + 2*p    ] = v.x;
            pp[(tr*8+i)*NB + tc*8 + 2*p + 1] = v.y;
        }
}

// ---------------- K5: deterministic split-K reduce ----------------
__global__ __launch_bounds__(256) void k5_reduce(float* __restrict__ y)
{
    int o = blockIdx.x*256 + threadIdx.x;   // 16384 outputs
    float s = 0.f;
    #pragma unroll 4
    for (int ks = 0; ks < KSPLIT; ks++)
        s += g_part[(size_t)ks*NB*NB + o];
    y[o] = s;
}

// ---------------- launcher ----------------
extern "C" void kernel_launch(void* const* d_in, const int* in_sizes, int n_in,
                              void* d_out, int out_size)
{
    const float* x    = (const float*)d_in[0];   // 128 x 16384
    const float* filt = (const float*)d_in[1];   // 4096 x 1024
    const float* w1   = (const float*)d_in[2];   // 128 x 128
    const float* w2   = (const float*)d_in[3];   // 256 x 128 x 25
    const float* beta = (const float*)d_in[4];   // 128 x 49408
    float* y = (float*)d_out;                    // 128 x 128

    static int smem_set = 0;
    if (!smem_set) {
        cudaFuncSetAttribute(k3_conv2_mma, cudaFuncAttributeMaxDynamicSharedMemorySize,
                             K3_SMEM_TOTAL);
        smem_set = 1;
    }

    k0_w2b  <<<NK3, 256>>>(w2);
    k1_spec <<<dim3(25, 8), 256>>>(x, filt);
    k2_conv1<<<dim3(NB*NRG, 2), 256>>>(w1);
    k3_conv2_mma<<<dim3(KSPLIT, 2), 256, K3_SMEM_TOTAL>>>();
    k4_beta <<<KSPLIT, 256>>>(beta);
    k5_reduce<<<NB*NB/256, 256>>>(y);
}

// round 13
// speedup vs baseline: 4.0346x; 1.2846x over previous
#include <cuda_runtime.h>
#include <cuda_bf16.h>
#include <cstdint>
#include <math.h>

// ---------------- problem constants ----------------
#define NB    128      // batch
#define WIN   16384
#define DD    4096     // window length (GEMM1 K)
#define HOP   512
#define NRG   25       // NUM_REGIONS
#define NF    1024     // 2*K filters output cols
#define KF    512      // K (spectrogram bins)
#define NW    193      // NR2Y
#define NK2   128      // conv1 out channels
#define D2Y   128      // conv1 kernel width
#define NK3   256      // conv2 out channels
#define D3X   25       // conv2 kernel height
#define KK3   3200     // NK2*D3X (conv2 reduction)
#define NFLAT 49408    // NK3*NW
#define KSPLIT 193
#define KCH   256      // NFLAT / KSPLIT

typedef unsigned long long ull;

// ---------------- packed f32x2 helpers (sm_103a FFMA2) ----------------
__device__ __forceinline__ ull ffma2(ull a, ull b, ull c) {
    ull d;
    asm("fma.rn.f32x2 %0, %1, %2, %3;" : "=l"(d) : "l"(a), "l"(b), "l"(c));
    return d;
}
__device__ __forceinline__ ull bcast2(float x) {
    ull d; unsigned u = __float_as_uint(x);
    asm("mov.b64 %0, {%1, %1};" : "=l"(d) : "r"(u));
    return d;
}
__device__ __forceinline__ float2 unpk2(ull v) {
    unsigned lo, hi;
    asm("mov.b64 {%0, %1}, %2;" : "=r"(lo), "=r"(hi) : "l"(v));
    return make_float2(__uint_as_float(lo), __uint_as_float(hi));
}

// ---------------- bf16 split helper ----------------
__device__ __forceinline__ void bf16split(float r, unsigned short &h, unsigned short &l) {
    __nv_bfloat16 bh = __float2bfloat16(r);
    float lo = r - __bfloat162float(bh);
    h = __bfloat16_as_ushort(bh);
    l = __bfloat16_as_ushort(__float2bfloat16(lo));
}

// ---------------- mma.sync bf16 (sm_80+ baseline; works at compute_103) ----
__device__ __forceinline__ void mma16816(float* c, const unsigned* a, unsigned b0, unsigned b1) {
    asm volatile(
        "mma.sync.aligned.m16n8k16.row.col.f32.bf16.bf16.f32 "
        "{%0,%1,%2,%3}, {%4,%5,%6,%7}, {%8,%9}, {%0,%1,%2,%3};"
        : "+f"(c[0]), "+f"(c[1]), "+f"(c[2]), "+f"(c[3])
        : "r"(a[0]), "r"(a[1]), "r"(a[2]), "r"(a[3]), "r"(b0), "r"(b1));
}

// ---------------- scratch (device globals: allocation-free) ----------------
__device__ float g_zx[NB*NRG*KF];                         // [b*25+h][512]
__device__ unsigned short g_xh[(size_t)NB*WIN];           // bf16 hi of x
__device__ unsigned short g_xl[(size_t)NB*WIN];           // bf16 lo of x
__device__ unsigned short g_fh[(size_t)NF*DD];            // filters^T hi [n][k]
__device__ unsigned short g_fl[(size_t)NF*DD];            // filters^T lo
__device__ unsigned short g_h1h[(size_t)NB*D3X*NW*NK2];   // bf16 hi [b][dx][w][k2]
__device__ unsigned short g_h1l[(size_t)NB*D3X*NW*NK2];   // bf16 lo
__device__ unsigned short g_w2h[(size_t)NK3*KK3];         // bf16 hi [k3][kk]
__device__ unsigned short g_w2l[(size_t)NK3*KK3];         // bf16 lo
__device__ float g_h2[NB*NK3*NW];                         // [b][k3*193+w]  (post-relu)
__device__ float g_part[KSPLIT*NB*NB];                    // [ks][b][m]

// ---------------- K0a: x -> bf16 hi/lo ----------------
__global__ __launch_bounds__(256) void k0_x(const float* __restrict__ x)
{
    int i = blockIdx.x*256 + threadIdx.x;     // 2M elements
    unsigned short h, l; bf16split(x[i], h, l);
    g_xh[i] = h; g_xl[i] = l;
}

// ---------------- K0b: filters -> transpose + bf16 hi/lo, [n][k] -----------
__global__ __launch_bounds__(256) void k0_filt(const float* __restrict__ filt)
{
    __shared__ float tile[32][33];
    const int k0 = blockIdx.x*32, n0 = blockIdx.y*32;
    const int tr = threadIdx.x >> 5, tc = threadIdx.x & 31;
    #pragma unroll
    for (int r = tr; r < 32; r += 8)
        tile[r][tc] = filt[(size_t)(k0+r)*NF + n0 + tc];
    __syncthreads();
    #pragma unroll
    for (int r = tr; r < 32; r += 8) {
        float v = tile[tc][r];                // filt[k0+tc][n0+r]
        unsigned short h, l; bf16split(v, h, l);
        g_fh[(size_t)(n0+r)*DD + k0 + tc] = h;
        g_fl[(size_t)(n0+r)*DD + k0 + tc] = l;
    }
}

// ---------------- K0c: w2 -> bf16 hi/lo, [k3][kk=dx*128+k2] K-major --------
__global__ __launch_bounds__(256) void k0_w2b(const float* __restrict__ w2)
{
    int k3 = blockIdx.x;           // 0..255
    for (int kk = threadIdx.x; kk < KK3; kk += 256) {
        float v = w2[((k3 << 7) + (kk & 127))*D3X + (kk >> 7)];
        unsigned short h, l; bf16split(v, h, l);
        g_w2h[(size_t)k3*KK3 + kk] = h;
        g_w2l[(size_t)k3*KK3 + kk] = l;
    }
}

// ---------------- shared GEMM smem geometry (k1/k3) ----------------
#define MM_SA     72                          // padded row stride (bf16)
#define MM_TILE_B (128*MM_SA*2)               // 18432 bytes per tile
#define MM_SMEM_TOTAL (4*MM_TILE_B)           // 73728 bytes

// ---------------- K1: spec GEMM via mma.sync bf16-split + |.|^2 + log ------
// C[3200][1024] = windows(x) @ filters; CTA 128x128, warp 64x32, K-chunks 64.
__global__ __launch_bounds__(256) void k1_spec_mma()
{
    extern __shared__ char smem[];
    unsigned short* sAh = (unsigned short*)(smem);
    unsigned short* sAl = (unsigned short*)(smem + MM_TILE_B);
    unsigned short* sBh = (unsigned short*)(smem + 2*MM_TILE_B);
    unsigned short* sBl = (unsigned short*)(smem + 3*MM_TILE_B);
    const unsigned* uAh = (const unsigned*)sAh;
    const unsigned* uAl = (const unsigned*)sAl;
    const unsigned* uBh = (const unsigned*)sBh;
    const unsigned* uBl = (const unsigned*)sBl;

    const int tid = threadIdx.x;
    const int wid = tid >> 5, lane = tid & 31;
    const int g = lane >> 2, tg = lane & 3;
    const int wm = wid >> 2, wn = wid & 3;       // 2 x 4 warp grid
    const int m0 = blockIdx.x * 128;
    const int n0 = blockIdx.y * 128;

    size_t aoff[4]; int asm_[4];
    #pragma unroll
    for (int i=0;i<4;i++){
        int e = tid + i*256;           // 1024 uint4 of A tile
        int row = e >> 3, c8 = e & 7;
        int m = m0 + row;
        int b = m / NRG, h = m % NRG;
        aoff[i] = (size_t)b*WIN + (size_t)h*HOP + c8*8;
        asm_[i] = row*9 + c8;
    }
    size_t boff[4]; int bsm[4];
    #pragma unroll
    for (int i=0;i<4;i++){
        int e = tid + i*256;
        int n = e >> 3, c8 = e & 7;
        boff[i] = (size_t)(n0 + n)*DD + c8*8;
        bsm[i] = n*9 + c8;
    }

    float acc[4][4][4];
    #pragma unroll
    for (int mt=0;mt<4;mt++)
        #pragma unroll
        for (int nt=0;nt<4;nt++)
            #pragma unroll
            for (int q=0;q<4;q++) acc[mt][nt][q]=0.f;

    const int aRowBase = wm*64 + g;
    const int bRowBase = wn*32 + g;

    for (int t = 0; t < DD/64; t++) {        // 64 chunks
        const size_t o = (size_t)t*64;

        uint4 rah[4], ral[4], rbh[4], rbl[4];
        #pragma unroll
        for (int i=0;i<4;i++){
            rah[i] = *(const uint4*)(g_xh + aoff[i] + o);
            ral[i] = *(const uint4*)(g_xl + aoff[i] + o);
            rbh[i] = *(const uint4*)(g_fh + boff[i] + o);
            rbl[i] = *(const uint4*)(g_fl + boff[i] + o);
        }
        __syncthreads();
        #pragma unroll
        for (int i=0;i<4;i++){
            ((uint4*)sAh)[asm_[i]] = rah[i];
            ((uint4*)sAl)[asm_[i]] = ral[i];
            ((uint4*)sBh)[bsm[i]] = rbh[i];
            ((uint4*)sBl)[bsm[i]] = rbl[i];
        }
        __syncthreads();

        #pragma unroll
        for (int kt=0;kt<4;kt++){
            const int kc = kt*8 + tg;
            unsigned bh0[4], bh1[4], bl0[4], bl1[4];
            #pragma unroll
            for (int nt=0;nt<4;nt++){
                int bi = (bRowBase + nt*8)*36 + kc;
                bh0[nt] = uBh[bi];     bh1[nt] = uBh[bi + 4];
                bl0[nt] = uBl[bi];     bl1[nt] = uBl[bi + 4];
            }
            #pragma unroll
            for (int mt=0;mt<4;mt++){
                int ai0 = (aRowBase + mt*16)*36 + kc;
                int ai1 = ai0 + 8*36;
                unsigned ah[4] = {uAh[ai0], uAh[ai1], uAh[ai0+4], uAh[ai1+4]};
                unsigned al[4] = {uAl[ai0], uAl[ai1], uAl[ai0+4], uAl[ai1+4]};
                #pragma unroll
                for (int nt=0;nt<4;nt++){
                    mma16816(acc[mt][nt], ah, bh0[nt], bh1[nt]);
                    mma16816(acc[mt][nt], ah, bl0[nt], bl1[nt]);
                    mma16816(acc[mt][nt], al, bh0[nt], bh1[nt]);
                }
            }
        }
    }

    // epilogue: (c0,c1) and (c2,c3) are (cos,sin) pairs -> power -> log
    #pragma unroll
    for (int mt=0;mt<4;mt++){
        int m_lo = m0 + wm*64 + mt*16 + g;
        int m_hi = m_lo + 8;
        #pragma unroll
        for (int nt=0;nt<4;nt++){
            int zc = (n0 >> 1) + wn*16 + nt*4 + tg;
            float c0 = acc[mt][nt][0], c1 = acc[mt][nt][1];
            float c2 = acc[mt][nt][2], c3 = acc[mt][nt][3];
            g_zx[m_lo*KF + zc] = logf(fmaf(c0,c0,c1*c1) + 1e-14f);
            g_zx[m_hi*KF + zc] = logf(fmaf(c2,c2,c3*c3) + 1e-14f);
        }
    }
}

// ---------------- K2: conv1 (1x128 stride 2) + relu -> bf16 hi/lo h1 -------
__global__ __launch_bounds__(256,2) void k2_conv1(const float* __restrict__ w1)
{
    __shared__ __align__(16) float ze[320];
    __shared__ __align__(16) float zo[320];
    __shared__ __align__(16) float w1th[D2Y][68];
    const int tid = threadIdx.x;
    const int bh  = blockIdx.x;
    const int n0h = blockIdx.y * 64;
    const int b = bh / NRG, h = bh % NRG;

    if (tid < 128) {
        float4 v = *(const float4*)&g_zx[bh*KF + tid*4];
        *(float2*)&ze[2*tid] = make_float2(v.x, v.z);
        *(float2*)&zo[2*tid] = make_float2(v.y, v.w);
    } else if (tid < 192) {
        ze[256 + tid-128] = 0.f;
        zo[256 + tid-128] = 0.f;
    }
    #pragma unroll
    for (int it = 0; it < 8; it++) {
        int e = tid + it*256;
        int k2l = e >> 5, j4 = e & 31;
        float4 v = *(const float4*)&w1[(n0h + k2l)*D2Y + j4*4];
        w1th[j4*4+0][k2l] = v.x;
        w1th[j4*4+1][k2l] = v.y;
        w1th[j4*4+2][k2l] = v.z;
        w1th[j4*4+3][k2l] = v.w;
    }
    __syncthreads();

    const int tr = tid >> 4;
    const int tc = tid & 15;
    const int tcK = tc*4;
    const size_t Ebase = (size_t)(b*D3X + h)*NW*NK2 + n0h + tcK;

    for (int wt = 0; wt < 2; wt++) {
        const int wbase = wt*128 + tr*8;
        ull acc[8][2];
        #pragma unroll
        for (int i=0;i<8;i++){ acc[i][0]=0ull; acc[i][1]=0ull; }
        ull pe[8], po[8];
        #pragma unroll
        for (int i=0;i<8;i++){ pe[i]=bcast2(ze[wbase+i]); po[i]=bcast2(zo[wbase+i]); }

        #define K2_STEP(S) { \
            const int j = 2*(u0+(S)); \
            ulonglong2 qe = *(const ulonglong2*)&w1th[j  ][tcK]; \
            ulonglong2 qo = *(const ulonglong2*)&w1th[j+1][tcK]; \
            _Pragma("unroll") \
            for (int i=0;i<8;i++){ \
                ull a_e = pe[((S)+i)&7], a_o = po[((S)+i)&7]; \
                acc[i][0] = ffma2(a_e, qe.x, acc[i][0]); \
                acc[i][1] = ffma2(a_e, qe.y, acc[i][1]); \
                acc[i][0] = ffma2(a_o, qo.x, acc[i][0]); \
                acc[i][1] = ffma2(a_o, qo.y, acc[i][1]); \
            } \
            pe[(S)&7] = bcast2(ze[wbase + 8 + u0+(S)]); \
            po[(S)&7] = bcast2(zo[wbase + 8 + u0+(S)]); \
        }
        for (int u0 = 0; u0 < 64; u0 += 8) {
            K2_STEP(0) K2_STEP(1) K2_STEP(2) K2_STEP(3)
            K2_STEP(4) K2_STEP(5) K2_STEP(6) K2_STEP(7)
        }
        #undef K2_STEP

        #pragma unroll
        for (int i=0;i<8;i++){
            int w = wbase + i;
            if (w < NW) {
                float2 v0 = unpk2(acc[i][0]);
                float2 v1 = unpk2(acc[i][1]);
                float r[4] = {fmaxf(v0.x,0.f), fmaxf(v0.y,0.f),
                              fmaxf(v1.x,0.f), fmaxf(v1.y,0.f)};
                unsigned short hh[4], ll[4];
                #pragma unroll
                for (int j=0;j<4;j++) bf16split(r[j], hh[j], ll[j]);
                ull ph = (ull)hh[0] | ((ull)hh[1]<<16) | ((ull)hh[2]<<32) | ((ull)hh[3]<<48);
                ull pl = (ull)ll[0] | ((ull)ll[1]<<16) | ((ull)ll[2]<<32) | ((ull)ll[3]<<48);
                size_t E = Ebase + (size_t)w*NK2;
                *(ull*)(g_h1h + E) = ph;
                *(ull*)(g_h1l + E) = pl;
            }
        }
    }
}

// ---------------- K3: conv2 GEMM via mma.sync bf16-split + relu ------------
__global__ __launch_bounds__(256) void k3_conv2_mma()
{
    extern __shared__ char smem[];
    unsigned short* sAh = (unsigned short*)(smem);
    unsigned short* sAl = (unsigned short*)(smem + MM_TILE_B);
    unsigned short* sBh = (unsigned short*)(smem + 2*MM_TILE_B);
    unsigned short* sBl = (unsigned short*)(smem + 3*MM_TILE_B);
    const unsigned* uAh = (const unsigned*)sAh;
    const unsigned* uAl = (const unsigned*)sAl;
    const unsigned* uBh = (const unsigned*)sBh;
    const unsigned* uBl = (const unsigned*)sBl;

    const int tid = threadIdx.x;
    const int wid = tid >> 5, lane = tid & 31;
    const int g = lane >> 2, tg = lane & 3;
    const int wm = wid >> 2, wn = wid & 3;
    const int m0 = blockIdx.x * 128;
    const int n0 = blockIdx.y * 128;

    size_t aoff[4]; int asm_[4];
    #pragma unroll
    for (int i=0;i<4;i++){
        int e = tid + i*256;
        int row = e >> 3, c8 = e & 7;
        int m = m0 + row;
        int b = m / NW, w = m % NW;
        aoff[i] = (size_t)b*617600 + (size_t)w*128 + c8*8;
        asm_[i] = row*9 + c8;
    }
    size_t boff[4]; int bsm[4];
    #pragma unroll
    for (int i=0;i<4;i++){
        int e = tid + i*256;
        int n = e >> 3, c8 = e & 7;
        boff[i] = (size_t)(n0 + n)*KK3 + c8*8;
        bsm[i] = n*9 + c8;
    }

    float acc[4][4][4];
    #pragma unroll
    for (int mt=0;mt<4;mt++)
        #pragma unroll
        for (int nt=0;nt<4;nt++)
            #pragma unroll
            for (int q=0;q<4;q++) acc[mt][nt][q]=0.f;

    const int aRowBase = wm*64 + g;
    const int bRowBase = wn*32 + g;

    for (int t = 0; t < 50; t++) {
        const int dx = t >> 1, k2b = (t & 1) * 64;
        const size_t ao = (size_t)dx*24704 + k2b;
        const size_t bo = (size_t)t*64;

        uint4 rah[4], ral[4], rbh[4], rbl[4];
        #pragma unroll
        for (int i=0;i<4;i++){
            rah[i] = *(const uint4*)(g_h1h + aoff[i] + ao);
            ral[i] = *(const uint4*)(g_h1l + aoff[i] + ao);
            rbh[i] = *(const uint4*)(g_w2h + boff[i] + bo);
            rbl[i] = *(const uint4*)(g_w2l + boff[i] + bo);
        }
        __syncthreads();
        #pragma unroll
        for (int i=0;i<4;i++){
            ((uint4*)sAh)[asm_[i]] = rah[i];
            ((uint4*)sAl)[asm_[i]] = ral[i];
            ((uint4*)sBh)[bsm[i]] = rbh[i];
            ((uint4*)sBl)[bsm[i]] = rbl[i];
        }
        __syncthreads();

        #pragma unroll
        for (int kt=0;kt<4;kt++){
            const int kc = kt*8 + tg;
            unsigned bh0[4], bh1[4], bl0[4], bl1[4];
            #pragma unroll
            for (int nt=0;nt<4;nt++){
                int bi = (bRowBase + nt*8)*36 + kc;
                bh0[nt] = uBh[bi];     bh1[nt] = uBh[bi + 4];
                bl0[nt] = uBl[bi];     bl1[nt] = uBl[bi + 4];
            }
            #pragma unroll
            for (int mt=0;mt<4;mt++){
                int ai0 = (aRowBase + mt*16)*36 + kc;
                int ai1 = ai0 + 8*36;
                unsigned ah[4] = {uAh[ai0], uAh[ai1], uAh[ai0+4], uAh[ai1+4]};
                unsigned al[4] = {uAl[ai0], uAl[ai1], uAl[ai0+4], uAl[ai1+4]};
                #pragma unroll
                for (int nt=0;nt<4;nt++){
                    mma16816(acc[mt][nt], ah, bh0[nt], bh1[nt]);
                    mma16816(acc[mt][nt], ah, bl0[nt], bl1[nt]);
                    mma16816(acc[mt][nt], al, bh0[nt], bh1[nt]);
                }
            }
        }
    }

    #pragma unroll
    for (int mt=0;mt<4;mt++){
        int m_lo = m0 + wm*64 + mt*16 + g;
        int b_lo = m_lo / NW, w_lo = m_lo % NW;
        int m_hi = m_lo + 8;
        int b_hi = m_hi / NW, w_hi = m_hi % NW;
        #pragma unroll
        for (int nt=0;nt<4;nt++){
            int k3 = n0 + wn*32 + nt*8 + tg*2;
            g_h2[(size_t)(b_lo*NK3 + k3  )*NW + w_lo] = fmaxf(acc[mt][nt][0], 0.f);
            g_h2[(size_t)(b_lo*NK3 + k3+1)*NW + w_lo] = fmaxf(acc[mt][nt][1], 0.f);
            g_h2[(size_t)(b_hi*NK3 + k3  )*NW + w_hi] = fmaxf(acc[mt][nt][2], 0.f);
            g_h2[(size_t)(b_hi*NK3 + k3+1)*NW + w_hi] = fmaxf(acc[mt][nt][3], 0.f);
        }
    }
}

// ---------------- K4: split-K beta matmul partials ----------------
__global__ __launch_bounds__(256) void k4_beta(const float* __restrict__ beta)
{
    __shared__ __align__(16) float As[16][132];   // [k][b]
    __shared__ __align__(16) float Bs[16][132];   // [k][m]
    const int tid = threadIdx.x;
    const int ks = blockIdx.x;
    const int i0base = ks * KCH;
    const int tr = tid >> 4, tc = tid & 15;

    ull acc[8][4];
    #pragma unroll
    for (int i=0;i<8;i++)
        #pragma unroll
        for (int p=0;p<4;p++) acc[i][p]=0ull;

    for (int kit = 0; kit < 16; kit++) {
        int i0 = i0base + kit*16;
        float4 av[2], bv[2];
        #pragma unroll
        for (int it=0; it<2; it++){
            int e = tid + it*256;
            int rl = e >> 2, k4 = e & 3;
            av[it] = *(const float4*)(g_h2 + (size_t)rl*NFLAT + i0 + k4*4);
            bv[it] = *(const float4*)(beta + (size_t)rl*NFLAT + i0 + k4*4);
        }
        __syncthreads();
        #pragma unroll
        for (int it=0; it<2; it++){
            int e = tid + it*256;
            int rl = e >> 2, k4 = e & 3;
            As[k4*4+0][rl]=av[it].x; As[k4*4+1][rl]=av[it].y;
            As[k4*4+2][rl]=av[it].z; As[k4*4+3][rl]=av[it].w;
            Bs[k4*4+0][rl]=bv[it].x; Bs[k4*4+1][rl]=bv[it].y;
            Bs[k4*4+2][rl]=bv[it].z; Bs[k4*4+3][rl]=bv[it].w;
        }
        __syncthreads();
        #pragma unroll
        for (int k=0;k<16;k++){
            float4 a0 = *(const float4*)&As[k][tr*8];
            float4 a1 = *(const float4*)&As[k][tr*8+4];
            ull pa[8] = {bcast2(a0.x), bcast2(a0.y), bcast2(a0.z), bcast2(a0.w),
                         bcast2(a1.x), bcast2(a1.y), bcast2(a1.z), bcast2(a1.w)};
            ulonglong2 q0 = *(const ulonglong2*)&Bs[k][tc*8];
            ulonglong2 q1 = *(const ulonglong2*)&Bs[k][tc*8+4];
            ull rb[4] = {q0.x, q0.y, q1.x, q1.y};
            #pragma unroll
            for (int i=0;i<8;i++)
                #pragma unroll
                for (int p=0;p<4;p++)
                    acc[i][p] = ffma2(pa[i], rb[p], acc[i][p]);
        }
    }
    float* pp = g_part + (size_t)ks*NB*NB;
    #pragma unroll
    for (int i=0;i<8;i++)
        #pragma unroll
        for (int p=0;p<4;p++){
            float2 v = unpk2(acc[i][p]);
            pp[(tr*8+i)*NB + tc*8 + 2*p    ] = v.x;
            pp[(tr*8+i)*NB + tc*8 + 2*p + 1] = v.y;
        }
}

// ---------------- K5: deterministic split-K reduce ----------------
__global__ __launch_bounds__(256) void k5_reduce(float* __restrict__ y)
{
    int o = blockIdx.x*256 + threadIdx.x;   // 16384 outputs
    float s = 0.f;
    #pragma unroll 4
    for (int ks = 0; ks < KSPLIT; ks++)
        s += g_part[(size_t)ks*NB*NB + o];
    y[o] = s;
}

// ---------------- launcher ----------------
extern "C" void kernel_launch(void* const* d_in, const int* in_sizes, int n_in,
                              void* d_out, int out_size)
{
    const float* x    = (const float*)d_in[0];   // 128 x 16384
    const float* filt = (const float*)d_in[1];   // 4096 x 1024
    const float* w1   = (const float*)d_in[2];   // 128 x 128
    const float* w2   = (const float*)d_in[3];   // 256 x 128 x 25
    const float* beta = (const float*)d_in[4];   // 128 x 49408
    float* y = (float*)d_out;                    // 128 x 128

    static int smem_set = 0;
    if (!smem_set) {
        cudaFuncSetAttribute(k1_spec_mma, cudaFuncAttributeMaxDynamicSharedMemorySize,
                             MM_SMEM_TOTAL);
        cudaFuncSetAttribute(k3_conv2_mma, cudaFuncAttributeMaxDynamicSharedMemorySize,
                             MM_SMEM_TOTAL);
        smem_set = 1;
    }

    k0_x    <<<NB*WIN/256, 256>>>(x);
    k0_filt <<<dim3(DD/32, NF/32), 256>>>(filt);
    k0_w2b  <<<NK3, 256>>>(w2);
    k1_spec_mma<<<dim3(25, 8), 256, MM_SMEM_TOTAL>>>();
    k2_conv1<<<dim3(NB*NRG, 2), 256>>>(w1);
    k3_conv2_mma<<<dim3(KSPLIT, 2), 256, MM_SMEM_TOTAL>>>();
    k4_beta <<<KSPLIT, 256>>>(beta);
    k5_reduce<<<NB*NB/256, 256>>>(y);
}

// round 15
// speedup vs baseline: 4.2920x; 1.0638x over previous
#include <cuda_runtime.h>
#include <cuda_bf16.h>
#include <cstdint>
#include <math.h>

// ---------------- problem constants ----------------
#define NB    128      // batch
#define WIN   16384
#define DD    4096     // window length (GEMM1 K)
#define HOP   512
#define NRG   25       // NUM_REGIONS
#define NF    1024     // 2*K filters output cols
#define KF    512      // K (spectrogram bins)
#define NW    193      // NR2Y
#define NK2   128      // conv1 out channels
#define D2Y   128      // conv1 kernel width
#define NK3   256      // conv2 out channels
#define D3X   25       // conv2 kernel height
#define KK3   3200     // NK2*D3X (conv2 reduction)
#define NFLAT 49408    // NK3*NW
#define KSPLIT 193
#define KCH   256      // NFLAT / KSPLIT

typedef unsigned long long ull;

// ---------------- packed f32x2 helpers (sm_103a FFMA2) ----------------
__device__ __forceinline__ ull ffma2(ull a, ull b, ull c) {
    ull d;
    asm("fma.rn.f32x2 %0, %1, %2, %3;" : "=l"(d) : "l"(a), "l"(b), "l"(c));
    return d;
}
__device__ __forceinline__ ull bcast2(float x) {
    ull d; unsigned u = __float_as_uint(x);
    asm("mov.b64 %0, {%1, %1};" : "=l"(d) : "r"(u));
    return d;
}
__device__ __forceinline__ float2 unpk2(ull v) {
    unsigned lo, hi;
    asm("mov.b64 {%0, %1}, %2;" : "=r"(lo), "=r"(hi) : "l"(v));
    return make_float2(__uint_as_float(lo), __uint_as_float(hi));
}

// ---------------- bf16 split helper ----------------
__device__ __forceinline__ void bf16split(float r, unsigned short &h, unsigned short &l) {
    __nv_bfloat16 bh = __float2bfloat16(r);
    float lo = r - __bfloat162float(bh);
    h = __bfloat16_as_ushort(bh);
    l = __bfloat16_as_ushort(__float2bfloat16(lo));
}

// ---------------- mma.sync bf16 + cp.async ----------------
__device__ __forceinline__ void mma16816(float* c, const unsigned* a, unsigned b0, unsigned b1) {
    asm volatile(
        "mma.sync.aligned.m16n8k16.row.col.f32.bf16.bf16.f32 "
        "{%0,%1,%2,%3}, {%4,%5,%6,%7}, {%8,%9}, {%0,%1,%2,%3};"
        : "+f"(c[0]), "+f"(c[1]), "+f"(c[2]), "+f"(c[3])
        : "r"(a[0]), "r"(a[1]), "r"(a[2]), "r"(a[3]), "r"(b0), "r"(b1));
}
__device__ __forceinline__ uint32_t smem_u32(const void* p) {
    uint32_t a;
    asm("{ .reg .u64 t; cvta.to.shared.u64 t, %1; cvt.u32.u64 %0, t; }" : "=r"(a) : "l"(p));
    return a;
}
#define CP_ASYNC16(sm, gp) asm volatile("cp.async.cg.shared.global [%0], [%1], 16;" :: "r"(sm), "l"(gp))
#define CP_COMMIT()        asm volatile("cp.async.commit_group;" ::: "memory")
#define CP_WAIT1()         asm volatile("cp.async.wait_group 1;" ::: "memory")
#define CP_WAIT0()         asm volatile("cp.async.wait_group 0;" ::: "memory")

// ---------------- scratch (device globals: allocation-free) ----------------
__device__ float g_zx[NB*NRG*KF];                         // [b*25+h][512]
__device__ unsigned short g_xh[(size_t)NB*WIN];           // bf16 hi of x
__device__ unsigned short g_xl[(size_t)NB*WIN];           // bf16 lo of x
__device__ unsigned short g_fh[(size_t)NF*DD];            // filters^T hi [n][k]
__device__ unsigned short g_fl[(size_t)NF*DD];            // filters^T lo
__device__ unsigned short g_h1h[(size_t)NB*D3X*NW*NK2];   // bf16 hi [b][dx][w][k2]
__device__ unsigned short g_h1l[(size_t)NB*D3X*NW*NK2];   // bf16 lo
__device__ unsigned short g_w2h[(size_t)NK3*KK3];         // bf16 hi [k3][kk]
__device__ unsigned short g_w2l[(size_t)NK3*KK3];         // bf16 lo
__device__ float g_h2[NB*NK3*NW];                         // [b][k3*193+w]  (post-relu)
__device__ float g_part[KSPLIT*NB*NB];                    // [ks][b][m]

// ---------------- K0a: x -> bf16 hi/lo ----------------
__global__ __launch_bounds__(256) void k0_x(const float* __restrict__ x)
{
    int i = blockIdx.x*256 + threadIdx.x;     // 2M elements
    unsigned short h, l; bf16split(x[i], h, l);
    g_xh[i] = h; g_xl[i] = l;
}

// ---------------- K0b: filters -> transpose + bf16 hi/lo, [n][k] -----------
__global__ __launch_bounds__(256) void k0_filt(const float* __restrict__ filt)
{
    __shared__ float tile[32][33];
    const int k0 = blockIdx.x*32, n0 = blockIdx.y*32;
    const int tr = threadIdx.x >> 5, tc = threadIdx.x & 31;
    #pragma unroll
    for (int r = tr; r < 32; r += 8)
        tile[r][tc] = filt[(size_t)(k0+r)*NF + n0 + tc];
    __syncthreads();
    #pragma unroll
    for (int r = tr; r < 32; r += 8) {
        float v = tile[tc][r];                // filt[k0+tc][n0+r]
        unsigned short h, l; bf16split(v, h, l);
        g_fh[(size_t)(n0+r)*DD + k0 + tc] = h;
        g_fl[(size_t)(n0+r)*DD + k0 + tc] = l;
    }
}

// ---------------- K0c: w2 -> bf16 hi/lo, [k3][kk=dx*128+k2] K-major --------
__global__ __launch_bounds__(256) void k0_w2b(const float* __restrict__ w2)
{
    int k3 = blockIdx.x;           // 0..255
    for (int kk = threadIdx.x; kk < KK3; kk += 256) {
        float v = w2[((k3 << 7) + (kk & 127))*D3X + (kk >> 7)];
        unsigned short h, l; bf16split(v, h, l);
        g_w2h[(size_t)k3*KK3 + kk] = h;
        g_w2l[(size_t)k3*KK3 + kk] = l;
    }
}

// ---------------- shared GEMM smem geometry (k1/k3) ----------------
#define MM_SA     72                          // padded row stride (bf16)
#define MM_TILE_B (128*MM_SA*2)               // 18432 bytes per tile
#define MM_BUF_B  (4*MM_TILE_B)               // 73728 bytes per stage
#define MM_SMEM_TOTAL (2*MM_BUF_B)            // 147456 bytes (double buffer)

// ---------------- K1: spec GEMM via mma.sync bf16-split + |.|^2 + log ------
// C[3200][1024] = windows(x) @ filters; CTA 128x128, warp 64x32, K-chunks 64.
__global__ __launch_bounds__(256) void k1_spec_mma()
{
    extern __shared__ char smem[];
    const uint32_t sbase = smem_u32(smem);

    const int tid = threadIdx.x;
    const int wid = tid >> 5, lane = tid & 31;
    const int g = lane >> 2, tg = lane & 3;
    const int wm = wid >> 2, wn = wid & 3;       // 2 x 4 warp grid
    const int m0 = blockIdx.x * 128;
    const int n0 = blockIdx.y * 128;

    size_t aoff[4]; uint32_t asmB[4];
    #pragma unroll
    for (int i=0;i<4;i++){
        int e = tid + i*256;           // 1024 uint4 of A tile
        int row = e >> 3, c8 = e & 7;
        int m = m0 + row;
        int b = m / NRG, h = m % NRG;
        aoff[i] = (size_t)b*WIN + (size_t)h*HOP + c8*8;
        asmB[i] = (row*9 + c8)*16;
    }
    size_t boff[4]; uint32_t bsmB[4];
    #pragma unroll
    for (int i=0;i<4;i++){
        int e = tid + i*256;
        int n = e >> 3, c8 = e & 7;
        boff[i] = (size_t)(n0 + n)*DD + c8*8;
        bsmB[i] = (n*9 + c8)*16;
    }

    float acc[4][4][4];
    #pragma unroll
    for (int mt=0;mt<4;mt++)
        #pragma unroll
        for (int nt=0;nt<4;nt++)
            #pragma unroll
            for (int q=0;q<4;q++) acc[mt][nt][q]=0.f;

    const int aRowBase = wm*64 + g;
    const int bRowBase = wn*32 + g;
    const int NT = DD/64;  // 64

    // prologue: prefetch chunk 0 into stage 0
    {
        uint32_t s = sbase;
        #pragma unroll
        for (int i=0;i<4;i++){
            CP_ASYNC16(s + 0*MM_TILE_B + asmB[i], g_xh + aoff[i]);
            CP_ASYNC16(s + 1*MM_TILE_B + asmB[i], g_xl + aoff[i]);
            CP_ASYNC16(s + 2*MM_TILE_B + bsmB[i], g_fh + boff[i]);
            CP_ASYNC16(s + 3*MM_TILE_B + bsmB[i], g_fl + boff[i]);
        }
        CP_COMMIT();
    }

    for (int t = 0; t < NT; t++) {
        if (t+1 < NT) {
            const size_t o = (size_t)(t+1)*64;
            uint32_t s = sbase + ((t+1)&1)*MM_BUF_B;
            #pragma unroll
            for (int i=0;i<4;i++){
                CP_ASYNC16(s + 0*MM_TILE_B + asmB[i], g_xh + aoff[i] + o);
                CP_ASYNC16(s + 1*MM_TILE_B + asmB[i], g_xl + aoff[i] + o);
                CP_ASYNC16(s + 2*MM_TILE_B + bsmB[i], g_fh + boff[i] + o);
                CP_ASYNC16(s + 3*MM_TILE_B + bsmB[i], g_fl + boff[i] + o);
            }
            CP_COMMIT();
            CP_WAIT1();
        } else {
            CP_WAIT0();
        }
        __syncthreads();

        const char* buf = smem + (t&1)*MM_BUF_B;
        const unsigned* uAh = (const unsigned*)(buf);
        const unsigned* uAl = (const unsigned*)(buf + MM_TILE_B);
        const unsigned* uBh = (const unsigned*)(buf + 2*MM_TILE_B);
        const unsigned* uBl = (const unsigned*)(buf + 3*MM_TILE_B);

        #pragma unroll
        for (int kt=0;kt<4;kt++){
            const int kc = kt*8 + tg;
            unsigned bh0[4], bh1[4], bl0[4], bl1[4];
            #pragma unroll
            for (int nt=0;nt<4;nt++){
                int bi = (bRowBase + nt*8)*36 + kc;
                bh0[nt] = uBh[bi];     bh1[nt] = uBh[bi + 4];
                bl0[nt] = uBl[bi];     bl1[nt] = uBl[bi + 4];
            }
            #pragma unroll
            for (int mt=0;mt<4;mt++){
                int ai0 = (aRowBase + mt*16)*36 + kc;
                int ai1 = ai0 + 8*36;
                unsigned ah[4] = {uAh[ai0], uAh[ai1], uAh[ai0+4], uAh[ai1+4]};
                unsigned al[4] = {uAl[ai0], uAl[ai1], uAl[ai0+4], uAl[ai1+4]};
                #pragma unroll
                for (int nt=0;nt<4;nt++){
                    mma16816(acc[mt][nt], ah, bh0[nt], bh1[nt]);
                    mma16816(acc[mt][nt], ah, bl0[nt], bl1[nt]);
                    mma16816(acc[mt][nt], al, bh0[nt], bh1[nt]);
                }
            }
        }
        __syncthreads();
    }

    // epilogue: (c0,c1) and (c2,c3) are (cos,sin) pairs -> power -> log
    #pragma unroll
    for (int mt=0;mt<4;mt++){
        int m_lo = m0 + wm*64 + mt*16 + g;
        int m_hi = m_lo + 8;
        #pragma unroll
        for (int nt=0;nt<4;nt++){
            int zc = (n0 >> 1) + wn*16 + nt*4 + tg;
            float c0 = acc[mt][nt][0], c1 = acc[mt][nt][1];
            float c2 = acc[mt][nt][2], c3 = acc[mt][nt][3];
            g_zx[m_lo*KF + zc] = logf(fmaf(c0,c0,c1*c1) + 1e-14f);
            g_zx[m_hi*KF + zc] = logf(fmaf(c2,c2,c3*c3) + 1e-14f);
        }
    }
}

// ---------------- K2: conv1 (1x128 stride 2) + relu -> bf16 hi/lo h1 -------
__global__ __launch_bounds__(256,2) void k2_conv1(const float* __restrict__ w1)
{
    __shared__ __align__(16) float ze[320];
    __shared__ __align__(16) float zo[320];
    __shared__ __align__(16) float w1th[D2Y][68];
    const int tid = threadIdx.x;
    const int bh  = blockIdx.x;
    const int n0h = blockIdx.y * 64;
    const int b = bh / NRG, h = bh % NRG;

    if (tid < 128) {
        float4 v = *(const float4*)&g_zx[bh*KF + tid*4];
        *(float2*)&ze[2*tid] = make_float2(v.x, v.z);
        *(float2*)&zo[2*tid] = make_float2(v.y, v.w);
    } else if (tid < 192) {
        ze[256 + tid-128] = 0.f;
        zo[256 + tid-128] = 0.f;
    }
    #pragma unroll
    for (int it = 0; it < 8; it++) {
        int e = tid + it*256;
        int k2l = e >> 5, j4 = e & 31;
        float4 v = *(const float4*)&w1[(n0h + k2l)*D2Y + j4*4];
        w1th[j4*4+0][k2l] = v.x;
        w1th[j4*4+1][k2l] = v.y;
        w1th[j4*4+2][k2l] = v.z;
        w1th[j4*4+3][k2l] = v.w;
    }
    __syncthreads();

    const int tr = tid >> 4;
    const int tc = tid & 15;
    const int tcK = tc*4;
    const size_t Ebase = (size_t)(b*D3X + h)*NW*NK2 + n0h + tcK;

    for (int wt = 0; wt < 2; wt++) {
        const int wbase = wt*128 + tr*8;
        ull acc[8][2];
        #pragma unroll
        for (int i=0;i<8;i++){ acc[i][0]=0ull; acc[i][1]=0ull; }
        ull pe[8], po[8];
        #pragma unroll
        for (int i=0;i<8;i++){ pe[i]=bcast2(ze[wbase+i]); po[i]=bcast2(zo[wbase+i]); }

        #define K2_STEP(S) { \
            const int j = 2*(u0+(S)); \
            ulonglong2 qe = *(const ulonglong2*)&w1th[j  ][tcK]; \
            ulonglong2 qo = *(const ulonglong2*)&w1th[j+1][tcK]; \
            _Pragma("unroll") \
            for (int i=0;i<8;i++){ \
                ull a_e = pe[((S)+i)&7], a_o = po[((S)+i)&7]; \
                acc[i][0] = ffma2(a_e, qe.x, acc[i][0]); \
                acc[i][1] = ffma2(a_e, qe.y, acc[i][1]); \
                acc[i][0] = ffma2(a_o, qo.x, acc[i][0]); \
                acc[i][1] = ffma2(a_o, qo.y, acc[i][1]); \
            } \
            pe[(S)&7] = bcast2(ze[wbase + 8 + u0+(S)]); \
            po[(S)&7] = bcast2(zo[wbase + 8 + u0+(S)]); \
        }
        for (int u0 = 0; u0 < 64; u0 += 8) {
            K2_STEP(0) K2_STEP(1) K2_STEP(2) K2_STEP(3)
            K2_STEP(4) K2_STEP(5) K2_STEP(6) K2_STEP(7)
        }
        #undef K2_STEP

        #pragma unroll
        for (int i=0;i<8;i++){
            int w = wbase + i;
            if (w < NW) {
                float2 v0 = unpk2(acc[i][0]);
                float2 v1 = unpk2(acc[i][1]);
                float r[4] = {fmaxf(v0.x,0.f), fmaxf(v0.y,0.f),
                              fmaxf(v1.x,0.f), fmaxf(v1.y,0.f)};
                unsigned short hh[4], ll[4];
                #pragma unroll
                for (int j=0;j<4;j++) bf16split(r[j], hh[j], ll[j]);
                ull ph = (ull)hh[0] | ((ull)hh[1]<<16) | ((ull)hh[2]<<32) | ((ull)hh[3]<<48);
                ull pl = (ull)ll[0] | ((ull)ll[1]<<16) | ((ull)ll[2]<<32) | ((ull)ll[3]<<48);
                size_t E = Ebase + (size_t)w*NK2;
                *(ull*)(g_h1h + E) = ph;
                *(ull*)(g_h1l + E) = pl;
            }
        }
    }
}

// ---------------- K3: conv2 GEMM via mma.sync bf16-split + relu ------------
__global__ __launch_bounds__(256) void k3_conv2_mma()
{
    extern __shared__ char smem[];
    const uint32_t sbase = smem_u32(smem);

    const int tid = threadIdx.x;
    const int wid = tid >> 5, lane = tid & 31;
    const int g = lane >> 2, tg = lane & 3;
    const int wm = wid >> 2, wn = wid & 3;
    const int m0 = blockIdx.x * 128;
    const int n0 = blockIdx.y * 128;

    size_t aoff[4]; uint32_t asmB[4];
    #pragma unroll
    for (int i=0;i<4;i++){
        int e = tid + i*256;
        int row = e >> 3, c8 = e & 7;
        int m = m0 + row;
        int b = m / NW, w = m % NW;
        aoff[i] = (size_t)b*617600 + (size_t)w*128 + c8*8;
        asmB[i] = (row*9 + c8)*16;
    }
    size_t boff[4]; uint32_t bsmB[4];
    #pragma unroll
    for (int i=0;i<4;i++){
        int e = tid + i*256;
        int n = e >> 3, c8 = e & 7;
        boff[i] = (size_t)(n0 + n)*KK3 + c8*8;
        bsmB[i] = (n*9 + c8)*16;
    }

    float acc[4][4][4];
    #pragma unroll
    for (int mt=0;mt<4;mt++)
        #pragma unroll
        for (int nt=0;nt<4;nt++)
            #pragma unroll
            for (int q=0;q<4;q++) acc[mt][nt][q]=0.f;

    const int aRowBase = wm*64 + g;
    const int bRowBase = wn*32 + g;

    // chunk t: A offset dx(t)*24704 + k2b(t), B offset t*64
    // prologue: chunk 0
    {
        uint32_t s = sbase;
        #pragma unroll
        for (int i=0;i<4;i++){
            CP_ASYNC16(s + 0*MM_TILE_B + asmB[i], g_h1h + aoff[i]);
            CP_ASYNC16(s + 1*MM_TILE_B + asmB[i], g_h1l + aoff[i]);
            CP_ASYNC16(s + 2*MM_TILE_B + bsmB[i], g_w2h + boff[i]);
            CP_ASYNC16(s + 3*MM_TILE_B + bsmB[i], g_w2l + boff[i]);
        }
        CP_COMMIT();
    }

    for (int t = 0; t < 50; t++) {
        if (t+1 < 50) {
            const int tn = t+1;
            const size_t ao = (size_t)(tn >> 1)*24704 + (tn & 1)*64;
            const size_t bo = (size_t)tn*64;
            uint32_t s = sbase + (tn&1)*MM_BUF_B;
            #pragma unroll
            for (int i=0;i<4;i++){
                CP_ASYNC16(s + 0*MM_TILE_B + asmB[i], g_h1h + aoff[i] + ao);
                CP_ASYNC16(s + 1*MM_TILE_B + asmB[i], g_h1l + aoff[i] + ao);
                CP_ASYNC16(s + 2*MM_TILE_B + bsmB[i], g_w2h + boff[i] + bo);
                CP_ASYNC16(s + 3*MM_TILE_B + bsmB[i], g_w2l + boff[i] + bo);
            }
            CP_COMMIT();
            CP_WAIT1();
        } else {
            CP_WAIT0();
        }
        __syncthreads();

        const char* buf = smem + (t&1)*MM_BUF_B;
        const unsigned* uAh = (const unsigned*)(buf);
        const unsigned* uAl = (const unsigned*)(buf + MM_TILE_B);
        const unsigned* uBh = (const unsigned*)(buf + 2*MM_TILE_B);
        const unsigned* uBl = (const unsigned*)(buf + 3*MM_TILE_B);

        #pragma unroll
        for (int kt=0;kt<4;kt++){
            const int kc = kt*8 + tg;
            unsigned bh0[4], bh1[4], bl0[4], bl1[4];
            #pragma unroll
            for (int nt=0;nt<4;nt++){
                int bi = (bRowBase + nt*8)*36 + kc;
                bh0[nt] = uBh[bi];     bh1[nt] = uBh[bi + 4];
                bl0[nt] = uBl[bi];     bl1[nt] = uBl[bi + 4];
            }
            #pragma unroll
            for (int mt=0;mt<4;mt++){
                int ai0 = (aRowBase + mt*16)*36 + kc;
                int ai1 = ai0 + 8*36;
                unsigned ah[4] = {uAh[ai0], uAh[ai1], uAh[ai0+4], uAh[ai1+4]};
                unsigned al[4] = {uAl[ai0], uAl[ai1], uAl[ai0+4], uAl[ai1+4]};
                #pragma unroll
                for (int nt=0;nt<4;nt++){
                    mma16816(acc[mt][nt], ah, bh0[nt], bh1[nt]);
                    mma16816(acc[mt][nt], ah, bl0[nt], bl1[nt]);
                    mma16816(acc[mt][nt], al, bh0[nt], bh1[nt]);
                }
            }
        }
        __syncthreads();
    }

    #pragma unroll
    for (int mt=0;mt<4;mt++){
        int m_lo = m0 + wm*64 + mt*16 + g;
        int b_lo = m_lo / NW, w_lo = m_lo % NW;
        int m_hi = m_lo + 8;
        int b_hi = m_hi / NW, w_hi = m_hi % NW;
        #pragma unroll
        for (int nt=0;nt<4;nt++){
            int k3 = n0 + wn*32 + nt*8 + tg*2;
            g_h2[(size_t)(b_lo*NK3 + k3  )*NW + w_lo] = fmaxf(acc[mt][nt][0], 0.f);
            g_h2[(size_t)(b_lo*NK3 + k3+1)*NW + w_lo] = fmaxf(acc[mt][nt][1], 0.f);
            g_h2[(size_t)(b_hi*NK3 + k3  )*NW + w_hi] = fmaxf(acc[mt][nt][2], 0.f);
            g_h2[(size_t)(b_hi*NK3 + k3+1)*NW + w_hi] = fmaxf(acc[mt][nt][3], 0.f);
        }
    }
}

// ---------------- K4: split-K beta matmul partials ----------------
__global__ __launch_bounds__(256) void k4_beta(const float* __restrict__ beta)
{
    __shared__ __align__(16) float As[16][132];   // [k][b]
    __shared__ __align__(16) float Bs[16][132];   // [k][m]
    const int tid = threadIdx.x;
    const int ks = blockIdx.x;
    const int i0base = ks * KCH;
    const int tr = tid >> 4, tc = tid & 15;

    ull acc[8][4];
    #pragma unroll
    for (int i=0;i<8;i++)
        #pragma unroll
        for (int p=0;p<4;p++) acc[i][p]=0ull;

    for (int kit = 0; kit < 16; kit++) {
        int i0 = i0base + kit*16;
        float4 av[2], bv[2];
        #pragma unroll
        for (int it=0; it<2; it++){
            int e = tid + it*256;
            int rl = e >> 2, k4 = e & 3;
            av[it] = *(const float4*)(g_h2 + (size_t)rl*NFLAT + i0 + k4*4);
            bv[it] = *(const float4*)(beta + (size_t)rl*NFLAT + i0 + k4*4);
        }
        __syncthreads();
        #pragma unroll
        for (int it=0; it<2; it++){
            int e = tid + it*256;
            int rl = e >> 2, k4 = e & 3;
            As[k4*4+0][rl]=av[it].x; As[k4*4+1][rl]=av[it].y;
            As[k4*4+2][rl]=av[it].z; As[k4*4+3][rl]=av[it].w;
            Bs[k4*4+0][rl]=bv[it].x; Bs[k4*4+1][rl]=bv[it].y;
            Bs[k4*4+2][rl]=bv[it].z; Bs[k4*4+3][rl]=bv[it].w;
        }
        __syncthreads();
        #pragma unroll
        for (int k=0;k<16;k++){
            float4 a0 = *(const float4*)&As[k][tr*8];
            float4 a1 = *(const float4*)&As[k][tr*8+4];
            ull pa[8] = {bcast2(a0.x), bcast2(a0.y), bcast2(a0.z), bcast2(a0.w),
                         bcast2(a1.x), bcast2(a1.y), bcast2(a1.z), bcast2(a1.w)};
            ulonglong2 q0 = *(const ulonglong2*)&Bs[k][tc*8];
            ulonglong2 q1 = *(const ulonglong2*)&Bs[k][tc*8+4];
            ull rb[4] = {q0.x, q0.y, q1.x, q1.y};
            #pragma unroll
            for (int i=0;i<8;i++)
                #pragma unroll
                for (int p=0;p<4;p++)
                    acc[i][p] = ffma2(pa[i], rb[p], acc[i][p]);
        }
    }
    float* pp = g_part + (size_t)ks*NB*NB;
    #pragma unroll
    for (int i=0;i<8;i++)
        #pragma unroll
        for (int p=0;p<4;p++){
            float2 v = unpk2(acc[i][p]);
            pp[(tr*8+i)*NB + tc*8 + 2*p    ] = v.x;
            pp[(tr*8+i)*NB + tc*8 + 2*p + 1] = v.y;
        }
}

// ---------------- K5: deterministic split-K reduce ----------------
__global__ __launch_bounds__(256) void k5_reduce(float* __restrict__ y)
{
    int o = blockIdx.x*256 + threadIdx.x;   // 16384 outputs
    float s = 0.f;
    #pragma unroll 4
    for (int ks = 0; ks < KSPLIT; ks++)
        s += g_part[(size_t)ks*NB*NB + o];
    y[o] = s;
}

// ---------------- launcher ----------------
extern "C" void kernel_launch(void* const* d_in, const int* in_sizes, int n_in,
                              void* d_out, int out_size)
{
    const float* x    = (const float*)d_in[0];   // 128 x 16384
    const float* filt = (const float*)d_in[1];   // 4096 x 1024
    const float* w1   = (const float*)d_in[2];   // 128 x 128
    const float* w2   = (const float*)d_in[3];   // 256 x 128 x 25
    const float* beta = (const float*)d_in[4];   // 128 x 49408
    float* y = (float*)d_out;                    // 128 x 128

    static int smem_set = 0;
    if (!smem_set) {
        cudaFuncSetAttribute(k1_spec_mma, cudaFuncAttributeMaxDynamicSharedMemorySize,
                             MM_SMEM_TOTAL);
        cudaFuncSetAttribute(k3_conv2_mma, cudaFuncAttributeMaxDynamicSharedMemorySize,
                             MM_SMEM_TOTAL);
        smem_set = 1;
    }

    k0_x    <<<NB*WIN/256, 256>>>(x);
    k0_filt <<<dim3(DD/32, NF/32), 256>>>(filt);
    k0_w2b  <<<NK3, 256>>>(w2);
    k1_spec_mma<<<dim3(25, 8), 256, MM_SMEM_TOTAL>>>();
    k2_conv1<<<dim3(NB*NRG, 2), 256>>>(w1);
    k3_conv2_mma<<<dim3(KSPLIT, 2), 256, MM_SMEM_TOTAL>>>();
    k4_beta <<<KSPLIT, 256>>>(beta);
    k5_reduce<<<NB*NB/256, 256>>>(y);
}

// round 16
// speedup vs baseline: 4.5656x; 1.0637x over previous
#include <cuda_runtime.h>
#include <cuda_bf16.h>
#include <cstdint>
#include <math.h>

// ---------------- problem constants ----------------
#define NB    128      // batch
#define WIN   16384
#define DD    4096     // window length (GEMM1 K)
#define HOP   512
#define NRG   25       // NUM_REGIONS
#define NF    1024     // 2*K filters output cols
#define KF    512      // K (spectrogram bins)
#define NW    193      // NR2Y
#define NK2   128      // conv1 out channels
#define D2Y   128      // conv1 kernel width
#define NK3   256      // conv2 out channels
#define D3X   25       // conv2 kernel height
#define KK3   3200     // NK2*D3X (conv2 reduction)
#define NFLAT 49408    // NK3*NW
#define KSPLIT 193
#define KCH   256      // NFLAT / KSPLIT

typedef unsigned long long ull;

// ---------------- packed f32x2 helpers (sm_103a FFMA2) ----------------
__device__ __forceinline__ ull ffma2(ull a, ull b, ull c) {
    ull d;
    asm("fma.rn.f32x2 %0, %1, %2, %3;" : "=l"(d) : "l"(a), "l"(b), "l"(c));
    return d;
}
__device__ __forceinline__ ull bcast2(float x) {
    ull d; unsigned u = __float_as_uint(x);
    asm("mov.b64 %0, {%1, %1};" : "=l"(d) : "r"(u));
    return d;
}
__device__ __forceinline__ float2 unpk2(ull v) {
    unsigned lo, hi;
    asm("mov.b64 {%0, %1}, %2;" : "=r"(lo), "=r"(hi) : "l"(v));
    return make_float2(__uint_as_float(lo), __uint_as_float(hi));
}

// ---------------- bf16 split helper ----------------
__device__ __forceinline__ void bf16split(float r, unsigned short &h, unsigned short &l) {
    __nv_bfloat16 bh = __float2bfloat16(r);
    float lo = r - __bfloat162float(bh);
    h = __bfloat16_as_ushort(bh);
    l = __bfloat16_as_ushort(__float2bfloat16(lo));
}

// ---------------- mma.sync bf16 + cp.async ----------------
__device__ __forceinline__ void mma16816(float* c, const unsigned* a, unsigned b0, unsigned b1) {
    asm volatile(
        "mma.sync.aligned.m16n8k16.row.col.f32.bf16.bf16.f32 "
        "{%0,%1,%2,%3}, {%4,%5,%6,%7}, {%8,%9}, {%0,%1,%2,%3};"
        : "+f"(c[0]), "+f"(c[1]), "+f"(c[2]), "+f"(c[3])
        : "r"(a[0]), "r"(a[1]), "r"(a[2]), "r"(a[3]), "r"(b0), "r"(b1));
}
__device__ __forceinline__ uint32_t smem_u32(const void* p) {
    uint32_t a;
    asm("{ .reg .u64 t; cvta.to.shared.u64 t, %1; cvt.u32.u64 %0, t; }" : "=r"(a) : "l"(p));
    return a;
}
#define CP_ASYNC16(sm, gp) asm volatile("cp.async.cg.shared.global [%0], [%1], 16;" :: "r"(sm), "l"(gp))
#define CP_COMMIT()        asm volatile("cp.async.commit_group;" ::: "memory")
#define CP_WAIT1()         asm volatile("cp.async.wait_group 1;" ::: "memory")
#define CP_WAIT0()         asm volatile("cp.async.wait_group 0;" ::: "memory")

// ---------------- scratch (device globals: allocation-free) ----------------
__device__ float g_zx[NB*NRG*KF];                         // [b*25+h][512]
__device__ unsigned short g_xh[(size_t)NB*WIN];           // bf16 hi of x
__device__ unsigned short g_xl[(size_t)NB*WIN];           // bf16 lo of x
__device__ unsigned short g_fh[(size_t)NF*DD];            // filters^T hi [n][k]
__device__ unsigned short g_fl[(size_t)NF*DD];            // filters^T lo
__device__ unsigned short g_h1h[(size_t)NB*D3X*NW*NK2];   // bf16 hi [b][dx][w][k2]
__device__ unsigned short g_h1l[(size_t)NB*D3X*NW*NK2];   // bf16 lo
__device__ unsigned short g_w2h[(size_t)NK3*KK3];         // bf16 hi [k3][kk]
__device__ unsigned short g_w2l[(size_t)NK3*KK3];         // bf16 lo
__device__ float g_h2[NB*NK3*NW];                         // [b][k3*193+w]  (post-relu)
__device__ float g_part[KSPLIT*NB*NB];                    // [ks][b][m]

// ---------------- K0a: x -> bf16 hi/lo ----------------
__global__ __launch_bounds__(256) void k0_x(const float* __restrict__ x)
{
    int i = blockIdx.x*256 + threadIdx.x;     // 2M elements
    unsigned short h, l; bf16split(x[i], h, l);
    g_xh[i] = h; g_xl[i] = l;
}

// ---------------- K0b: filters -> transpose + bf16 hi/lo, [n][k] -----------
__global__ __launch_bounds__(256) void k0_filt(const float* __restrict__ filt)
{
    __shared__ float tile[32][33];
    const int k0 = blockIdx.x*32, n0 = blockIdx.y*32;
    const int tr = threadIdx.x >> 5, tc = threadIdx.x & 31;
    #pragma unroll
    for (int r = tr; r < 32; r += 8)
        tile[r][tc] = filt[(size_t)(k0+r)*NF + n0 + tc];
    __syncthreads();
    #pragma unroll
    for (int r = tr; r < 32; r += 8) {
        float v = tile[tc][r];                // filt[k0+tc][n0+r]
        unsigned short h, l; bf16split(v, h, l);
        g_fh[(size_t)(n0+r)*DD + k0 + tc] = h;
        g_fl[(size_t)(n0+r)*DD + k0 + tc] = l;
    }
}

// ---------------- K0c: w2 -> bf16 hi/lo, [k3][kk=dx*128+k2] K-major --------
__global__ __launch_bounds__(256) void k0_w2b(const float* __restrict__ w2)
{
    int k3 = blockIdx.x;           // 0..255
    for (int kk = threadIdx.x; kk < KK3; kk += 256) {
        float v = w2[((k3 << 7) + (kk & 127))*D3X + (kk >> 7)];
        unsigned short h, l; bf16split(v, h, l);
        g_w2h[(size_t)k3*KK3 + kk] = h;
        g_w2l[(size_t)k3*KK3 + kk] = l;
    }
}

// ---------------- shared GEMM smem geometry (k1/k3) ----------------
#define MM_SA     72                          // padded row stride (bf16)
#define MM_TILE_B (128*MM_SA*2)               // 18432 bytes per tile
#define MM_BUF_B  (4*MM_TILE_B)               // 73728 bytes per stage
#define MM_SMEM_TOTAL (3*MM_BUF_B)            // 221184 bytes (3-stage ring)

// ---------------- K1: spec GEMM via mma.sync bf16-split + |.|^2 + log ------
// C[3200][1024] = windows(x) @ filters; CTA 128x128, 16 warps (4x4), warp 32x32.
__global__ __launch_bounds__(512) void k1_spec_mma()
{
    extern __shared__ char smem[];
    const uint32_t sbase = smem_u32(smem);

    const int tid = threadIdx.x;
    const int wid = tid >> 5, lane = tid & 31;
    const int g = lane >> 2, tg = lane & 3;
    const int wm = wid >> 2, wn = wid & 3;       // 4 x 4 warp grid
    const int m0 = blockIdx.x * 128;
    const int n0 = blockIdx.y * 128;

    size_t aoff[2]; uint32_t asmB[2];
    #pragma unroll
    for (int i=0;i<2;i++){
        int e = tid + i*512;           // 1024 uint4 of A tile
        int row = e >> 3, c8 = e & 7;
        int m = m0 + row;
        int b = m / NRG, h = m % NRG;
        aoff[i] = (size_t)b*WIN + (size_t)h*HOP + c8*8;
        asmB[i] = (row*9 + c8)*16;
    }
    size_t boff[2]; uint32_t bsmB[2];
    #pragma unroll
    for (int i=0;i<2;i++){
        int e = tid + i*512;
        int n = e >> 3, c8 = e & 7;
        boff[i] = (size_t)(n0 + n)*DD + c8*8;
        bsmB[i] = (n*9 + c8)*16;
    }

    float acc[2][4][4];
    #pragma unroll
    for (int mt=0;mt<2;mt++)
        #pragma unroll
        for (int nt=0;nt<4;nt++)
            #pragma unroll
            for (int q=0;q<4;q++) acc[mt][nt][q]=0.f;

    const int aRowBase = wm*32 + g;
    const int bRowBase = wn*32 + g;
    const int NT = DD/64;  // 64

    // prologue: prefetch chunk 0 into stage 0
    {
        uint32_t s = sbase;
        #pragma unroll
        for (int i=0;i<2;i++){
            CP_ASYNC16(s + 0*MM_TILE_B + asmB[i], g_xh + aoff[i]);
            CP_ASYNC16(s + 1*MM_TILE_B + asmB[i], g_xl + aoff[i]);
            CP_ASYNC16(s + 2*MM_TILE_B + bsmB[i], g_fh + boff[i]);
            CP_ASYNC16(s + 3*MM_TILE_B + bsmB[i], g_fl + boff[i]);
        }
        CP_COMMIT();
    }

    int stw = 1;   // stage to write (t+1)%3
    int str = 0;   // stage to read  t%3
    for (int t = 0; t < NT; t++) {
        if (t+1 < NT) {
            const size_t o = (size_t)(t+1)*64;
            uint32_t s = sbase + stw*MM_BUF_B;
            #pragma unroll
            for (int i=0;i<2;i++){
                CP_ASYNC16(s + 0*MM_TILE_B + asmB[i], g_xh + aoff[i] + o);
                CP_ASYNC16(s + 1*MM_TILE_B + asmB[i], g_xl + aoff[i] + o);
                CP_ASYNC16(s + 2*MM_TILE_B + bsmB[i], g_fh + boff[i] + o);
                CP_ASYNC16(s + 3*MM_TILE_B + bsmB[i], g_fl + boff[i] + o);
            }
            CP_COMMIT();
            CP_WAIT1();
        } else {
            CP_WAIT0();
        }
        __syncthreads();   // single barrier per chunk (3-stage ring makes the trailing one unnecessary)

        const char* buf = smem + str*MM_BUF_B;
        const unsigned* uAh = (const unsigned*)(buf);
        const unsigned* uAl = (const unsigned*)(buf + MM_TILE_B);
        const unsigned* uBh = (const unsigned*)(buf + 2*MM_TILE_B);
        const unsigned* uBl = (const unsigned*)(buf + 3*MM_TILE_B);

        #pragma unroll
        for (int kt=0;kt<4;kt++){
            const int kc = kt*8 + tg;
            unsigned bh0[4], bh1[4], bl0[4], bl1[4];
            #pragma unroll
            for (int nt=0;nt<4;nt++){
                int bi = (bRowBase + nt*8)*36 + kc;
                bh0[nt] = uBh[bi];     bh1[nt] = uBh[bi + 4];
                bl0[nt] = uBl[bi];     bl1[nt] = uBl[bi + 4];
            }
            #pragma unroll
            for (int mt=0;mt<2;mt++){
                int ai0 = (aRowBase + mt*16)*36 + kc;
                int ai1 = ai0 + 8*36;
                unsigned ah[4] = {uAh[ai0], uAh[ai1], uAh[ai0+4], uAh[ai1+4]};
                unsigned al[4] = {uAl[ai0], uAl[ai1], uAl[ai0+4], uAl[ai1+4]};
                #pragma unroll
                for (int nt=0;nt<4;nt++){
                    mma16816(acc[mt][nt], ah, bh0[nt], bh1[nt]);
                    mma16816(acc[mt][nt], ah, bl0[nt], bl1[nt]);
                    mma16816(acc[mt][nt], al, bh0[nt], bh1[nt]);
                }
            }
        }
        str = (str+1 == 3) ? 0 : str+1;
        stw = (stw+1 == 3) ? 0 : stw+1;
    }

    // epilogue: (c0,c1) and (c2,c3) are (cos,sin) pairs -> power -> log
    #pragma unroll
    for (int mt=0;mt<2;mt++){
        int m_lo = m0 + wm*32 + mt*16 + g;
        int m_hi = m_lo + 8;
        #pragma unroll
        for (int nt=0;nt<4;nt++){
            int zc = (n0 >> 1) + wn*16 + nt*4 + tg;
            float c0 = acc[mt][nt][0], c1 = acc[mt][nt][1];
            float c2 = acc[mt][nt][2], c3 = acc[mt][nt][3];
            g_zx[m_lo*KF + zc] = logf(fmaf(c0,c0,c1*c1) + 1e-14f);
            g_zx[m_hi*KF + zc] = logf(fmaf(c2,c2,c3*c3) + 1e-14f);
        }
    }
}

// ---------------- K2: conv1 (1x128 stride 2) + relu -> bf16 hi/lo h1 -------
__global__ __launch_bounds__(256,2) void k2_conv1(const float* __restrict__ w1)
{
    __shared__ __align__(16) float ze[320];
    __shared__ __align__(16) float zo[320];
    __shared__ __align__(16) float w1th[D2Y][68];
    const int tid = threadIdx.x;
    const int bh  = blockIdx.x;
    const int n0h = blockIdx.y * 64;
    const int b = bh / NRG, h = bh % NRG;

    if (tid < 128) {
        float4 v = *(const float4*)&g_zx[bh*KF + tid*4];
        *(float2*)&ze[2*tid] = make_float2(v.x, v.z);
        *(float2*)&zo[2*tid] = make_float2(v.y, v.w);
    } else if (tid < 192) {
        ze[256 + tid-128] = 0.f;
        zo[256 + tid-128] = 0.f;
    }
    #pragma unroll
    for (int it = 0; it < 8; it++) {
        int e = tid + it*256;
        int k2l = e >> 5, j4 = e & 31;
        float4 v = *(const float4*)&w1[(n0h + k2l)*D2Y + j4*4];
        w1th[j4*4+0][k2l] = v.x;
        w1th[j4*4+1][k2l] = v.y;
        w1th[j4*4+2][k2l] = v.z;
        w1th[j4*4+3][k2l] = v.w;
    }
    __syncthreads();

    const int tr = tid >> 4;
    const int tc = tid & 15;
    const int tcK = tc*4;
    const size_t Ebase = (size_t)(b*D3X + h)*NW*NK2 + n0h + tcK;

    for (int wt = 0; wt < 2; wt++) {
        const int wbase = wt*128 + tr*8;
        ull acc[8][2];
        #pragma unroll
        for (int i=0;i<8;i++){ acc[i][0]=0ull; acc[i][1]=0ull; }
        ull pe[8], po[8];
        #pragma unroll
        for (int i=0;i<8;i++){ pe[i]=bcast2(ze[wbase+i]); po[i]=bcast2(zo[wbase+i]); }

        #define K2_STEP(S) { \
            const int j = 2*(u0+(S)); \
            ulonglong2 qe = *(const ulonglong2*)&w1th[j  ][tcK]; \
            ulonglong2 qo = *(const ulonglong2*)&w1th[j+1][tcK]; \
            _Pragma("unroll") \
            for (int i=0;i<8;i++){ \
                ull a_e = pe[((S)+i)&7], a_o = po[((S)+i)&7]; \
                acc[i][0] = ffma2(a_e, qe.x, acc[i][0]); \
                acc[i][1] = ffma2(a_e, qe.y, acc[i][1]); \
                acc[i][0] = ffma2(a_o, qo.x, acc[i][0]); \
                acc[i][1] = ffma2(a_o, qo.y, acc[i][1]); \
            } \
            pe[(S)&7] = bcast2(ze[wbase + 8 + u0+(S)]); \
            po[(S)&7] = bcast2(zo[wbase + 8 + u0+(S)]); \
        }
        for (int u0 = 0; u0 < 64; u0 += 8) {
            K2_STEP(0) K2_STEP(1) K2_STEP(2) K2_STEP(3)
            K2_STEP(4) K2_STEP(5) K2_STEP(6) K2_STEP(7)
        }
        #undef K2_STEP

        #pragma unroll
        for (int i=0;i<8;i++){
            int w = wbase + i;
            if (w < NW) {
                float2 v0 = unpk2(acc[i][0]);
                float2 v1 = unpk2(acc[i][1]);
                float r[4] = {fmaxf(v0.x,0.f), fmaxf(v0.y,0.f),
                              fmaxf(v1.x,0.f), fmaxf(v1.y,0.f)};
                unsigned short hh[4], ll[4];
                #pragma unroll
                for (int j=0;j<4;j++) bf16split(r[j], hh[j], ll[j]);
                ull ph = (ull)hh[0] | ((ull)hh[1]<<16) | ((ull)hh[2]<<32) | ((ull)hh[3]<<48);
                ull pl = (ull)ll[0] | ((ull)ll[1]<<16) | ((ull)ll[2]<<32) | ((ull)ll[3]<<48);
                size_t E = Ebase + (size_t)w*NK2;
                *(ull*)(g_h1h + E) = ph;
                *(ull*)(g_h1l + E) = pl;
            }
        }
    }
}

// ---------------- K3: conv2 GEMM via mma.sync bf16-split + relu ------------
// CTA 128x128, 16 warps (4x4), warp 32x32, 3-stage ring, 1 barrier/chunk.
__global__ __launch_bounds__(512) void k3_conv2_mma()
{
    extern __shared__ char smem[];
    const uint32_t sbase = smem_u32(smem);

    const int tid = threadIdx.x;
    const int wid = tid >> 5, lane = tid & 31;
    const int g = lane >> 2, tg = lane & 3;
    const int wm = wid >> 2, wn = wid & 3;
    const int m0 = blockIdx.x * 128;
    const int n0 = blockIdx.y * 128;

    size_t aoff[2]; uint32_t asmB[2];
    #pragma unroll
    for (int i=0;i<2;i++){
        int e = tid + i*512;
        int row = e >> 3, c8 = e & 7;
        int m = m0 + row;
        int b = m / NW, w = m % NW;
        aoff[i] = (size_t)b*617600 + (size_t)w*128 + c8*8;
        asmB[i] = (row*9 + c8)*16;
    }
    size_t boff[2]; uint32_t bsmB[2];
    #pragma unroll
    for (int i=0;i<2;i++){
        int e = tid + i*512;
        int n = e >> 3, c8 = e & 7;
        boff[i] = (size_t)(n0 + n)*KK3 + c8*8;
        bsmB[i] = (n*9 + c8)*16;
    }

    float acc[2][4][4];
    #pragma unroll
    for (int mt=0;mt<2;mt++)
        #pragma unroll
        for (int nt=0;nt<4;nt++)
            #pragma unroll
            for (int q=0;q<4;q++) acc[mt][nt][q]=0.f;

    const int aRowBase = wm*32 + g;
    const int bRowBase = wn*32 + g;

    // prologue: chunk 0 -> stage 0
    {
        uint32_t s = sbase;
        #pragma unroll
        for (int i=0;i<2;i++){
            CP_ASYNC16(s + 0*MM_TILE_B + asmB[i], g_h1h + aoff[i]);
            CP_ASYNC16(s + 1*MM_TILE_B + asmB[i], g_h1l + aoff[i]);
            CP_ASYNC16(s + 2*MM_TILE_B + bsmB[i], g_w2h + boff[i]);
            CP_ASYNC16(s + 3*MM_TILE_B + bsmB[i], g_w2l + boff[i]);
        }
        CP_COMMIT();
    }

    int stw = 1, str = 0;
    for (int t = 0; t < 50; t++) {
        if (t+1 < 50) {
            const int tn = t+1;
            const size_t ao = (size_t)(tn >> 1)*24704 + (tn & 1)*64;
            const size_t bo = (size_t)tn*64;
            uint32_t s = sbase + stw*MM_BUF_B;
            #pragma unroll
            for (int i=0;i<2;i++){
                CP_ASYNC16(s + 0*MM_TILE_B + asmB[i], g_h1h + aoff[i] + ao);
                CP_ASYNC16(s + 1*MM_TILE_B + asmB[i], g_h1l + aoff[i] + ao);
                CP_ASYNC16(s + 2*MM_TILE_B + bsmB[i], g_w2h + boff[i] + bo);
                CP_ASYNC16(s + 3*MM_TILE_B + bsmB[i], g_w2l + boff[i] + bo);
            }
            CP_COMMIT();
            CP_WAIT1();
        } else {
            CP_WAIT0();
        }
        __syncthreads();

        const char* buf = smem + str*MM_BUF_B;
        const unsigned* uAh = (const unsigned*)(buf);
        const unsigned* uAl = (const unsigned*)(buf + MM_TILE_B);
        const unsigned* uBh = (const unsigned*)(buf + 2*MM_TILE_B);
        const unsigned* uBl = (const unsigned*)(buf + 3*MM_TILE_B);

        #pragma unroll
        for (int kt=0;kt<4;kt++){
            const int kc = kt*8 + tg;
            unsigned bh0[4], bh1[4], bl0[4], bl1[4];
            #pragma unroll
            for (int nt=0;nt<4;nt++){
                int bi = (bRowBase + nt*8)*36 + kc;
                bh0[nt] = uBh[bi];     bh1[nt] = uBh[bi + 4];
                bl0[nt] = uBl[bi];     bl1[nt] = uBl[bi + 4];
            }
            #pragma unroll
            for (int mt=0;mt<2;mt++){
                int ai0 = (aRowBase + mt*16)*36 + kc;
                int ai1 = ai0 + 8*36;
                unsigned ah[4] = {uAh[ai0], uAh[ai1], uAh[ai0+4], uAh[ai1+4]};
                unsigned al[4] = {uAl[ai0], uAl[ai1], uAl[ai0+4], uAl[ai1+4]};
                #pragma unroll
                for (int nt=0;nt<4;nt++){
                    mma16816(acc[mt][nt], ah, bh0[nt], bh1[nt]);
                    mma16816(acc[mt][nt], ah, bl0[nt], bl1[nt]);
                    mma16816(acc[mt][nt], al, bh0[nt], bh1[nt]);
                }
            }
        }
        str = (str+1 == 3) ? 0 : str+1;
        stw = (stw+1 == 3) ? 0 : stw+1;
    }

    #pragma unroll
    for (int mt=0;mt<2;mt++){
        int m_lo = m0 + wm*32 + mt*16 + g;
        int b_lo = m_lo / NW, w_lo = m_lo % NW;
        int m_hi = m_lo + 8;
        int b_hi = m_hi / NW, w_hi = m_hi % NW;
        #pragma unroll
        for (int nt=0;nt<4;nt++){
            int k3 = n0 + wn*32 + nt*8 + tg*2;
            g_h2[(size_t)(b_lo*NK3 + k3  )*NW + w_lo] = fmaxf(acc[mt][nt][0], 0.f);
            g_h2[(size_t)(b_lo*NK3 + k3+1)*NW + w_lo] = fmaxf(acc[mt][nt][1], 0.f);
            g_h2[(size_t)(b_hi*NK3 + k3  )*NW + w_hi] = fmaxf(acc[mt][nt][2], 0.f);
            g_h2[(size_t)(b_hi*NK3 + k3+1)*NW + w_hi] = fmaxf(acc[mt][nt][3], 0.f);
        }
    }
}

// ---------------- K4: split-K beta matmul partials ----------------
__global__ __launch_bounds__(256) void k4_beta(const float* __restrict__ beta)
{
    __shared__ __align__(16) float As[16][132];   // [k][b]
    __shared__ __align__(16) float Bs[16][132];   // [k][m]
    const int tid = threadIdx.x;
    const int ks = blockIdx.x;
    const int i0base = ks * KCH;
    const int tr = tid >> 4, tc = tid & 15;

    ull acc[8][4];
    #pragma unroll
    for (int i=0;i<8;i++)
        #pragma unroll
        for (int p=0;p<4;p++) acc[i][p]=0ull;

    for (int kit = 0; kit < 16; kit++) {
        int i0 = i0base + kit*16;
        float4 av[2], bv[2];
        #pragma unroll
        for (int it=0; it<2; it++){
            int e = tid + it*256;
            int rl = e >> 2, k4 = e & 3;
            av[it] = *(const float4*)(g_h2 + (size_t)rl*NFLAT + i0 + k4*4);
            bv[it] = *(const float4*)(beta + (size_t)rl*NFLAT + i0 + k4*4);
        }
        __syncthreads();
        #pragma unroll
        for (int it=0; it<2; it++){
            int e = tid + it*256;
            int rl = e >> 2, k4 = e & 3;
            As[k4*4+0][rl]=av[it].x; As[k4*4+1][rl]=av[it].y;
            As[k4*4+2][rl]=av[it].z; As[k4*4+3][rl]=av[it].w;
            Bs[k4*4+0][rl]=bv[it].x; Bs[k4*4+1][rl]=bv[it].y;
            Bs[k4*4+2][rl]=bv[it].z; Bs[k4*4+3][rl]=bv[it].w;
        }
        __syncthreads();
        #pragma unroll
        for (int k=0;k<16;k++){
            float4 a0 = *(const float4*)&As[k][tr*8];
            float4 a1 = *(const float4*)&As[k][tr*8+4];
            ull pa[8] = {bcast2(a0.x), bcast2(a0.y), bcast2(a0.z), bcast2(a0.w),
                         bcast2(a1.x), bcast2(a1.y), bcast2(a1.z), bcast2(a1.w)};
            ulonglong2 q0 = *(const ulonglong2*)&Bs[k][tc*8];
            ulonglong2 q1 = *(const ulonglong2*)&Bs[k][tc*8+4];
            ull rb[4] = {q0.x, q0.y, q1.x, q1.y};
            #pragma unroll
            for (int i=0;i<8;i++)
                #pragma unroll
                for (int p=0;p<4;p++)
                    acc[i][p] = ffma2(pa[i], rb[p], acc[i][p]);
        }
    }
    float* pp = g_part + (size_t)ks*NB*NB;
    #pragma unroll
    for (int i=0;i<8;i++)
        #pragma unroll
        for (int p=0;p<4;p++){
            float2 v = unpk2(acc[i][p]);
            pp[(tr*8+i)*NB + tc*8 + 2*p    ] = v.x;
            pp[(tr*8+i)*NB + tc*8 + 2*p + 1] = v.y;
        }
}

// ---------------- K5: deterministic split-K reduce ----------------
__global__ __launch_bounds__(256) void k5_reduce(float* __restrict__ y)
{
    int o = blockIdx.x*256 + threadIdx.x;   // 16384 outputs
    float s = 0.f;
    #pragma unroll 4
    for (int ks = 0; ks < KSPLIT; ks++)
        s += g_part[(size_t)ks*NB*NB + o];
    y[o] = s;
}

// ---------------- launcher ----------------
extern "C" void kernel_launch(void* const* d_in, const int* in_sizes, int n_in,
                              void* d_out, int out_size)
{
    const float* x    = (const float*)d_in[0];   // 128 x 16384
    const float* filt = (const float*)d_in[1];   // 4096 x 1024
    const float* w1   = (const float*)d_in[2];   // 128 x 128
    const float* w2   = (const float*)d_in[3];   // 256 x 128 x 25
    const float* beta = (const float*)d_in[4];   // 128 x 49408
    float* y = (float*)d_out;                    // 128 x 128

    static int smem_set = 0;
    if (!smem_set) {
        cudaFuncSetAttribute(k1_spec_mma, cudaFuncAttributeMaxDynamicSharedMemorySize,
                             MM_SMEM_TOTAL);
        cudaFuncSetAttribute(k3_conv2_mma, cudaFuncAttributeMaxDynamicSharedMemorySize,
                             MM_SMEM_TOTAL);
        smem_set = 1;
    }

    k0_x    <<<NB*WIN/256, 256>>>(x);
    k0_filt <<<dim3(DD/32, NF/32), 256>>>(filt);
    k0_w2b  <<<NK3, 256>>>(w2);
    k1_spec_mma<<<dim3(25, 8), 512, MM_SMEM_TOTAL>>>();
    k2_conv1<<<dim3(NB*NRG, 2), 256>>>(w1);
    k3_conv2_mma<<<dim3(KSPLIT, 2), 512, MM_SMEM_TOTAL>>>();
    k4_beta <<<KSPLIT, 256>>>(beta);
    k5_reduce<<<NB*NB/256, 256>>>(y);
}

// round 17
// speedup vs baseline: 4.6505x; 1.0186x over previous
#include <cuda_runtime.h>
#include <cuda_bf16.h>
#include <cstdint>
#include <math.h>

// ---------------- problem constants ----------------
#define NB    128      // batch
#define WIN   16384
#define DD    4096     // window length (GEMM1 K)
#define HOP   512
#define NRG   25       // NUM_REGIONS
#define NF    1024     // 2*K filters output cols
#define KF    512      // K (spectrogram bins)
#define NW    193      // NR2Y
#define NK2   128      // conv1 out channels
#define D2Y   128      // conv1 kernel width
#define NK3   256      // conv2 out channels
#define D3X   25       // conv2 kernel height
#define KK3   3200     // NK2*D3X (conv2 reduction)
#define NFLAT 49408    // NK3*NW
#define KSPLIT 193
#define KCH   256      // NFLAT / KSPLIT

typedef unsigned long long ull;

// ---------------- packed f32x2 helpers (sm_103a FFMA2) ----------------
__device__ __forceinline__ ull ffma2(ull a, ull b, ull c) {
    ull d;
    asm("fma.rn.f32x2 %0, %1, %2, %3;" : "=l"(d) : "l"(a), "l"(b), "l"(c));
    return d;
}
__device__ __forceinline__ ull bcast2(float x) {
    ull d; unsigned u = __float_as_uint(x);
    asm("mov.b64 %0, {%1, %1};" : "=l"(d) : "r"(u));
    return d;
}
__device__ __forceinline__ float2 unpk2(ull v) {
    unsigned lo, hi;
    asm("mov.b64 {%0, %1}, %2;" : "=r"(lo), "=r"(hi) : "l"(v));
    return make_float2(__uint_as_float(lo), __uint_as_float(hi));
}

// ---------------- bf16 split helper ----------------
__device__ __forceinline__ void bf16split(float r, unsigned short &h, unsigned short &l) {
    __nv_bfloat16 bh = __float2bfloat16(r);
    float lo = r - __bfloat162float(bh);
    h = __bfloat16_as_ushort(bh);
    l = __bfloat16_as_ushort(__float2bfloat16(lo));
}

// ---------------- mma.sync bf16 + cp.async + ldmatrix ----------------
__device__ __forceinline__ void mma16816(float* c, const unsigned* a, unsigned b0, unsigned b1) {
    asm volatile(
        "mma.sync.aligned.m16n8k16.row.col.f32.bf16.bf16.f32 "
        "{%0,%1,%2,%3}, {%4,%5,%6,%7}, {%8,%9}, {%0,%1,%2,%3};"
        : "+f"(c[0]), "+f"(c[1]), "+f"(c[2]), "+f"(c[3])
        : "r"(a[0]), "r"(a[1]), "r"(a[2]), "r"(a[3]), "r"(b0), "r"(b1));
}
__device__ __forceinline__ uint32_t smem_u32(const void* p) {
    uint32_t a;
    asm("{ .reg .u64 t; cvta.to.shared.u64 t, %1; cvt.u32.u64 %0, t; }" : "=r"(a) : "l"(p));
    return a;
}
#define CP_ASYNC16(sm, gp) asm volatile("cp.async.cg.shared.global [%0], [%1], 16;" :: "r"(sm), "l"(gp))
#define CP_COMMIT()        asm volatile("cp.async.commit_group;" ::: "memory")
#define CP_WAIT1()         asm volatile("cp.async.wait_group 1;" ::: "memory")
#define CP_WAIT0()         asm volatile("cp.async.wait_group 0;" ::: "memory")
#define LDSM_X4(r0, r1, r2, r3, addr) \
    asm volatile("ldmatrix.sync.aligned.m8n8.x4.shared.b16 {%0,%1,%2,%3}, [%4];" \
        : "=r"(r0), "=r"(r1), "=r"(r2), "=r"(r3) : "r"(addr))

// ---------------- scratch (device globals: allocation-free) ----------------
__device__ float g_zx[NB*NRG*KF];                         // [b*25+h][512]
__device__ unsigned short g_xh[(size_t)NB*WIN];           // bf16 hi of x
__device__ unsigned short g_xl[(size_t)NB*WIN];           // bf16 lo of x
__device__ unsigned short g_fh[(size_t)NF*DD];            // filters^T hi [n][k]
__device__ unsigned short g_fl[(size_t)NF*DD];            // filters^T lo
__device__ unsigned short g_h1h[(size_t)NB*D3X*NW*NK2];   // bf16 hi [b][dx][w][k2]
__device__ unsigned short g_h1l[(size_t)NB*D3X*NW*NK2];   // bf16 lo
__device__ unsigned short g_w2h[(size_t)NK3*KK3];         // bf16 hi [k3][kk]
__device__ unsigned short g_w2l[(size_t)NK3*KK3];         // bf16 lo
__device__ float g_h2[NB*NK3*NW];                         // [b][k3*193+w]  (post-relu)
__device__ float g_part[KSPLIT*NB*NB];                    // [ks][b][m]

// ---------------- K0a: x -> bf16 hi/lo ----------------
__global__ __launch_bounds__(256) void k0_x(const float* __restrict__ x)
{
    int i = blockIdx.x*256 + threadIdx.x;     // 2M elements
    unsigned short h, l; bf16split(x[i], h, l);
    g_xh[i] = h; g_xl[i] = l;
}

// ---------------- K0b: filters -> transpose + bf16 hi/lo, [n][k] -----------
__global__ __launch_bounds__(256) void k0_filt(const float* __restrict__ filt)
{
    __shared__ float tile[32][33];
    const int k0 = blockIdx.x*32, n0 = blockIdx.y*32;
    const int tr = threadIdx.x >> 5, tc = threadIdx.x & 31;
    #pragma unroll
    for (int r = tr; r < 32; r += 8)
        tile[r][tc] = filt[(size_t)(k0+r)*NF + n0 + tc];
    __syncthreads();
    #pragma unroll
    for (int r = tr; r < 32; r += 8) {
        float v = tile[tc][r];                // filt[k0+tc][n0+r]
        unsigned short h, l; bf16split(v, h, l);
        g_fh[(size_t)(n0+r)*DD + k0 + tc] = h;
        g_fl[(size_t)(n0+r)*DD + k0 + tc] = l;
    }
}

// ---------------- K0c: w2 -> bf16 hi/lo, [k3][kk=dx*128+k2] K-major --------
__global__ __launch_bounds__(256) void k0_w2b(const float* __restrict__ w2)
{
    int k3 = blockIdx.x;           // 0..255
    for (int kk = threadIdx.x; kk < KK3; kk += 256) {
        float v = w2[((k3 << 7) + (kk & 127))*D3X + (kk >> 7)];
        unsigned short h, l; bf16split(v, h, l);
        g_w2h[(size_t)k3*KK3 + kk] = h;
        g_w2l[(size_t)k3*KK3 + kk] = l;
    }
}

// ---------------- shared GEMM smem geometry (k1/k3) ----------------
#define MM_SA     72                          // padded row stride (bf16)
#define MM_RB     144                         // row stride bytes
#define MM_TILE_B (128*MM_SA*2)               // 18432 bytes per tile
#define MM_BUF_B  (4*MM_TILE_B)               // 73728 bytes per stage
#define MM_SMEM_TOTAL (3*MM_BUF_B)            // 221184 bytes (3-stage ring)

// ---------------- K1: spec GEMM via mma.sync bf16-split + |.|^2 + log ------
// C[3200][1024] = windows(x) @ filters; CTA 128x128, 16 warps (4x4), warp 32x32.
__global__ __launch_bounds__(512) void k1_spec_mma()
{
    extern __shared__ char smem[];
    const uint32_t sbase = smem_u32(smem);

    const int tid = threadIdx.x;
    const int wid = tid >> 5, lane = tid & 31;
    const int g = lane >> 2, tg = lane & 3;
    const int wm = wid >> 2, wn = wid & 3;       // 4 x 4 warp grid
    const int m0 = blockIdx.x * 128;
    const int n0 = blockIdx.y * 128;

    size_t aoff[2]; uint32_t asmB[2];
    #pragma unroll
    for (int i=0;i<2;i++){
        int e = tid + i*512;           // 1024 uint4 of A tile
        int row = e >> 3, c8 = e & 7;
        int m = m0 + row;
        int b = m / NRG, h = m % NRG;
        aoff[i] = (size_t)b*WIN + (size_t)h*HOP + c8*8;
        asmB[i] = (row*9 + c8)*16;
    }
    size_t boff[2]; uint32_t bsmB[2];
    #pragma unroll
    for (int i=0;i<2;i++){
        int e = tid + i*512;
        int n = e >> 3, c8 = e & 7;
        boff[i] = (size_t)(n0 + n)*DD + c8*8;
        bsmB[i] = (n*9 + c8)*16;
    }

    float acc[2][4][4];
    #pragma unroll
    for (int mt=0;mt<2;mt++)
        #pragma unroll
        for (int nt=0;nt<4;nt++)
            #pragma unroll
            for (int q=0;q<4;q++) acc[mt][nt][q]=0.f;

    // ldmatrix per-lane byte offsets within tiles
    const uint32_t aByte = (uint32_t)((wm*32 + (lane & 15))*MM_RB + ((lane >> 4) & 1)*16);
    const uint32_t bByte = (uint32_t)((wn*32 + (lane & 7) + ((lane >> 4) & 1)*8)*MM_RB
                                      + ((lane >> 3) & 1)*16);
    const int NT = DD/64;  // 64

    // prologue: prefetch chunk 0 into stage 0
    {
        uint32_t s = sbase;
        #pragma unroll
        for (int i=0;i<2;i++){
            CP_ASYNC16(s + 0*MM_TILE_B + asmB[i], g_xh + aoff[i]);
            CP_ASYNC16(s + 1*MM_TILE_B + asmB[i], g_xl + aoff[i]);
            CP_ASYNC16(s + 2*MM_TILE_B + bsmB[i], g_fh + boff[i]);
            CP_ASYNC16(s + 3*MM_TILE_B + bsmB[i], g_fl + boff[i]);
        }
        CP_COMMIT();
    }

    int stw = 1, str = 0;
    for (int t = 0; t < NT; t++) {
        if (t+1 < NT) {
            const size_t o = (size_t)(t+1)*64;
            uint32_t s = sbase + stw*MM_BUF_B;
            #pragma unroll
            for (int i=0;i<2;i++){
                CP_ASYNC16(s + 0*MM_TILE_B + asmB[i], g_xh + aoff[i] + o);
                CP_ASYNC16(s + 1*MM_TILE_B + asmB[i], g_xl + aoff[i] + o);
                CP_ASYNC16(s + 2*MM_TILE_B + bsmB[i], g_fh + boff[i] + o);
                CP_ASYNC16(s + 3*MM_TILE_B + bsmB[i], g_fl + boff[i] + o);
            }
            CP_COMMIT();
            CP_WAIT1();
        } else {
            CP_WAIT0();
        }
        __syncthreads();   // single barrier per chunk (3-stage ring)

        const uint32_t bufs = sbase + str*MM_BUF_B;
        const uint32_t aH = bufs + 0*MM_TILE_B + aByte;
        const uint32_t aL = bufs + 1*MM_TILE_B + aByte;
        const uint32_t bH = bufs + 2*MM_TILE_B + bByte;
        const uint32_t bL = bufs + 3*MM_TILE_B + bByte;

        #pragma unroll
        for (int kt=0;kt<4;kt++){
            const uint32_t ko = kt*32;
            unsigned bh0[4], bh1[4], bl0[4], bl1[4];
            LDSM_X4(bh0[0], bh1[0], bh0[1], bh1[1], bH + ko);
            LDSM_X4(bh0[2], bh1[2], bh0[3], bh1[3], bH + 16*MM_RB + ko);
            LDSM_X4(bl0[0], bl1[0], bl0[1], bl1[1], bL + ko);
            LDSM_X4(bl0[2], bl1[2], bl0[3], bl1[3], bL + 16*MM_RB + ko);
            #pragma unroll
            for (int mt=0;mt<2;mt++){
                unsigned ah[4], al[4];
                LDSM_X4(ah[0], ah[1], ah[2], ah[3], aH + mt*16*MM_RB + ko);
                LDSM_X4(al[0], al[1], al[2], al[3], aL + mt*16*MM_RB + ko);
                #pragma unroll
                for (int nt=0;nt<4;nt++){
                    mma16816(acc[mt][nt], ah, bh0[nt], bh1[nt]);
                    mma16816(acc[mt][nt], ah, bl0[nt], bl1[nt]);
                    mma16816(acc[mt][nt], al, bh0[nt], bh1[nt]);
                }
            }
        }
        str = (str+1 == 3) ? 0 : str+1;
        stw = (stw+1 == 3) ? 0 : stw+1;
    }

    // epilogue: (c0,c1) and (c2,c3) are (cos,sin) pairs -> power -> log
    #pragma unroll
    for (int mt=0;mt<2;mt++){
        int m_lo = m0 + wm*32 + mt*16 + g;
        int m_hi = m_lo + 8;
        #pragma unroll
        for (int nt=0;nt<4;nt++){
            int zc = (n0 >> 1) + wn*16 + nt*4 + tg;
            float c0 = acc[mt][nt][0], c1 = acc[mt][nt][1];
            float c2 = acc[mt][nt][2], c3 = acc[mt][nt][3];
            g_zx[m_lo*KF + zc] = logf(fmaf(c0,c0,c1*c1) + 1e-14f);
            g_zx[m_hi*KF + zc] = logf(fmaf(c2,c2,c3*c3) + 1e-14f);
        }
    }
}

// ---------------- K2: conv1 (1x128 stride 2) + relu -> bf16 hi/lo h1 -------
__global__ __launch_bounds__(256,2) void k2_conv1(const float* __restrict__ w1)
{
    __shared__ __align__(16) float ze[320];
    __shared__ __align__(16) float zo[320];
    __shared__ __align__(16) float w1th[D2Y][68];
    const int tid = threadIdx.x;
    const int bh  = blockIdx.x;
    const int n0h = blockIdx.y * 64;
    const int b = bh / NRG, h = bh % NRG;

    if (tid < 128) {
        float4 v = *(const float4*)&g_zx[bh*KF + tid*4];
        *(float2*)&ze[2*tid] = make_float2(v.x, v.z);
        *(float2*)&zo[2*tid] = make_float2(v.y, v.w);
    } else if (tid < 192) {
        ze[256 + tid-128] = 0.f;
        zo[256 + tid-128] = 0.f;
    }
    #pragma unroll
    for (int it = 0; it < 8; it++) {
        int e = tid + it*256;
        int k2l = e >> 5, j4 = e & 31;
        float4 v = *(const float4*)&w1[(n0h + k2l)*D2Y + j4*4];
        w1th[j4*4+0][k2l] = v.x;
        w1th[j4*4+1][k2l] = v.y;
        w1th[j4*4+2][k2l] = v.z;
        w1th[j4*4+3][k2l] = v.w;
    }
    __syncthreads();

    const int tr = tid >> 4;
    const int tc = tid & 15;
    const int tcK = tc*4;
    const size_t Ebase = (size_t)(b*D3X + h)*NW*NK2 + n0h + tcK;

    for (int wt = 0; wt < 2; wt++) {
        const int wbase = wt*128 + tr*8;
        ull acc[8][2];
        #pragma unroll
        for (int i=0;i<8;i++){ acc[i][0]=0ull; acc[i][1]=0ull; }
        ull pe[8], po[8];
        #pragma unroll
        for (int i=0;i<8;i++){ pe[i]=bcast2(ze[wbase+i]); po[i]=bcast2(zo[wbase+i]); }

        #define K2_STEP(S) { \
            const int j = 2*(u0+(S)); \
            ulonglong2 qe = *(const ulonglong2*)&w1th[j  ][tcK]; \
            ulonglong2 qo = *(const ulonglong2*)&w1th[j+1][tcK]; \
            _Pragma("unroll") \
            for (int i=0;i<8;i++){ \
                ull a_e = pe[((S)+i)&7], a_o = po[((S)+i)&7]; \
                acc[i][0] = ffma2(a_e, qe.x, acc[i][0]); \
                acc[i][1] = ffma2(a_e, qe.y, acc[i][1]); \
                acc[i][0] = ffma2(a_o, qo.x, acc[i][0]); \
                acc[i][1] = ffma2(a_o, qo.y, acc[i][1]); \
            } \
            pe[(S)&7] = bcast2(ze[wbase + 8 + u0+(S)]); \
            po[(S)&7] = bcast2(zo[wbase + 8 + u0+(S)]); \
        }
        for (int u0 = 0; u0 < 64; u0 += 8) {
            K2_STEP(0) K2_STEP(1) K2_STEP(2) K2_STEP(3)
            K2_STEP(4) K2_STEP(5) K2_STEP(6) K2_STEP(7)
        }
        #undef K2_STEP

        #pragma unroll
        for (int i=0;i<8;i++){
            int w = wbase + i;
            if (w < NW) {
                float2 v0 = unpk2(acc[i][0]);
                float2 v1 = unpk2(acc[i][1]);
                float r[4] = {fmaxf(v0.x,0.f), fmaxf(v0.y,0.f),
                              fmaxf(v1.x,0.f), fmaxf(v1.y,0.f)};
                unsigned short hh[4], ll[4];
                #pragma unroll
                for (int j=0;j<4;j++) bf16split(r[j], hh[j], ll[j]);
                ull ph = (ull)hh[0] | ((ull)hh[1]<<16) | ((ull)hh[2]<<32) | ((ull)hh[3]<<48);
                ull pl = (ull)ll[0] | ((ull)ll[1]<<16) | ((ull)ll[2]<<32) | ((ull)ll[3]<<48);
                size_t E = Ebase + (size_t)w*NK2;
                *(ull*)(g_h1h + E) = ph;
                *(ull*)(g_h1l + E) = pl;
            }
        }
    }
}

// ---------------- K3: conv2 GEMM via mma.sync bf16-split + relu ------------
// CTA 128x128, 16 warps (4x4), warp 32x32, 3-stage ring, ldmatrix fragments.
__global__ __launch_bounds__(512) void k3_conv2_mma()
{
    extern __shared__ char smem[];
    const uint32_t sbase = smem_u32(smem);

    const int tid = threadIdx.x;
    const int wid = tid >> 5, lane = tid & 31;
    const int g = lane >> 2, tg = lane & 3;
    const int wm = wid >> 2, wn = wid & 3;
    const int m0 = blockIdx.x * 128;
    const int n0 = blockIdx.y * 128;

    size_t aoff[2]; uint32_t asmB[2];
    #pragma unroll
    for (int i=0;i<2;i++){
        int e = tid + i*512;
        int row = e >> 3, c8 = e & 7;
        int m = m0 + row;
        int b = m / NW, w = m % NW;
        aoff[i] = (size_t)b*617600 + (size_t)w*128 + c8*8;
        asmB[i] = (row*9 + c8)*16;
    }
    size_t boff[2]; uint32_t bsmB[2];
    #pragma unroll
    for (int i=0;i<2;i++){
        int e = tid + i*512;
        int n = e >> 3, c8 = e & 7;
        boff[i] = (size_t)(n0 + n)*KK3 + c8*8;
        bsmB[i] = (n*9 + c8)*16;
    }

    float acc[2][4][4];
    #pragma unroll
    for (int mt=0;mt<2;mt++)
        #pragma unroll
        for (int nt=0;nt<4;nt++)
            #pragma unroll
            for (int q=0;q<4;q++) acc[mt][nt][q]=0.f;

    const uint32_t aByte = (uint32_t)((wm*32 + (lane & 15))*MM_RB + ((lane >> 4) & 1)*16);
    const uint32_t bByte = (uint32_t)((wn*32 + (lane & 7) + ((lane >> 4) & 1)*8)*MM_RB
                                      + ((lane >> 3) & 1)*16);

    // prologue: chunk 0 -> stage 0
    {
        uint32_t s = sbase;
        #pragma unroll
        for (int i=0;i<2;i++){
            CP_ASYNC16(s + 0*MM_TILE_B + asmB[i], g_h1h + aoff[i]);
            CP_ASYNC16(s + 1*MM_TILE_B + asmB[i], g_h1l + aoff[i]);
            CP_ASYNC16(s + 2*MM_TILE_B + bsmB[i], g_w2h + boff[i]);
            CP_ASYNC16(s + 3*MM_TILE_B + bsmB[i], g_w2l + boff[i]);
        }
        CP_COMMIT();
    }

    int stw = 1, str = 0;
    for (int t = 0; t < 50; t++) {
        if (t+1 < 50) {
            const int tn = t+1;
            const size_t ao = (size_t)(tn >> 1)*24704 + (tn & 1)*64;
            const size_t bo = (size_t)tn*64;
            uint32_t s = sbase + stw*MM_BUF_B;
            #pragma unroll
            for (int i=0;i<2;i++){
                CP_ASYNC16(s + 0*MM_TILE_B + asmB[i], g_h1h + aoff[i] + ao);
                CP_ASYNC16(s + 1*MM_TILE_B + asmB[i], g_h1l + aoff[i] + ao);
                CP_ASYNC16(s + 2*MM_TILE_B + bsmB[i], g_w2h + boff[i] + bo);
                CP_ASYNC16(s + 3*MM_TILE_B + bsmB[i], g_w2l + boff[i] + bo);
            }
            CP_COMMIT();
            CP_WAIT1();
        } else {
            CP_WAIT0();
        }
        __syncthreads();

        const uint32_t bufs = sbase + str*MM_BUF_B;
        const uint32_t aH = bufs + 0*MM_TILE_B + aByte;
        const uint32_t aL = bufs + 1*MM_TILE_B + aByte;
        const uint32_t bH = bufs + 2*MM_TILE_B + bByte;
        const uint32_t bL = bufs + 3*MM_TILE_B + bByte;

        #pragma unroll
        for (int kt=0;kt<4;kt++){
            const uint32_t ko = kt*32;
            unsigned bh0[4], bh1[4], bl0[4], bl1[4];
            LDSM_X4(bh0[0], bh1[0], bh0[1], bh1[1], bH + ko);
            LDSM_X4(bh0[2], bh1[2], bh0[3], bh1[3], bH + 16*MM_RB + ko);
            LDSM_X4(bl0[0], bl1[0], bl0[1], bl1[1], bL + ko);
            LDSM_X4(bl0[2], bl1[2], bl0[3], bl1[3], bL + 16*MM_RB + ko);
            #pragma unroll
            for (int mt=0;mt<2;mt++){
                unsigned ah[4], al[4];
                LDSM_X4(ah[0], ah[1], ah[2], ah[3], aH + mt*16*MM_RB + ko);
                LDSM_X4(al[0], al[1], al[2], al[3], aL + mt*16*MM_RB + ko);
                #pragma unroll
                for (int nt=0;nt<4;nt++){
                    mma16816(acc[mt][nt], ah, bh0[nt], bh1[nt]);
                    mma16816(acc[mt][nt], ah, bl0[nt], bl1[nt]);
                    mma16816(acc[mt][nt], al, bh0[nt], bh1[nt]);
                }
            }
        }
        str = (str+1 == 3) ? 0 : str+1;
        stw = (stw+1 == 3) ? 0 : stw+1;
    }

    #pragma unroll
    for (int mt=0;mt<2;mt++){
        int m_lo = m0 + wm*32 + mt*16 + g;
        int b_lo = m_lo / NW, w_lo = m_lo % NW;
        int m_hi = m_lo + 8;
        int b_hi = m_hi / NW, w_hi = m_hi % NW;
        #pragma unroll
        for (int nt=0;nt<4;nt++){
            int k3 = n0 + wn*32 + nt*8 + tg*2;
            g_h2[(size_t)(b_lo*NK3 + k3  )*NW + w_lo] = fmaxf(acc[mt][nt][0], 0.f);
            g_h2[(size_t)(b_lo*NK3 + k3+1)*NW + w_lo] = fmaxf(acc[mt][nt][1], 0.f);
            g_h2[(size_t)(b_hi*NK3 + k3  )*NW + w_hi] = fmaxf(acc[mt][nt][2], 0.f);
            g_h2[(size_t)(b_hi*NK3 + k3+1)*NW + w_hi] = fmaxf(acc[mt][nt][3], 0.f);
        }
    }
}

// ---------------- K4: split-K beta matmul partials ----------------
__global__ __launch_bounds__(256) void k4_beta(const float* __restrict__ beta)
{
    __shared__ __align__(16) float As[16][132];   // [k][b]
    __shared__ __align__(16) float Bs[16][132];   // [k][m]
    const int tid = threadIdx.x;
    const int ks = blockIdx.x;
    const int i0base = ks * KCH;
    const int tr = tid >> 4, tc = tid & 15;

    ull acc[8][4];
    #pragma unroll
    for (int i=0;i<8;i++)
        #pragma unroll
        for (int p=0;p<4;p++) acc[i][p]=0ull;

    for (int kit = 0; kit < 16; kit++) {
        int i0 = i0base + kit*16;
        float4 av[2], bv[2];
        #pragma unroll
        for (int it=0; it<2; it++){
            int e = tid + it*256;
            int rl = e >> 2, k4 = e & 3;
            av[it] = *(const float4*)(g_h2 + (size_t)rl*NFLAT + i0 + k4*4);
            bv[it] = *(const float4*)(beta + (size_t)rl*NFLAT + i0 + k4*4);
        }
        __syncthreads();
        #pragma unroll
        for (int it=0; it<2; it++){
            int e = tid + it*256;
            int rl = e >> 2, k4 = e & 3;
            As[k4*4+0][rl]=av[it].x; As[k4*4+1][rl]=av[it].y;
            As[k4*4+2][rl]=av[it].z; As[k4*4+3][rl]=av[it].w;
            Bs[k4*4+0][rl]=bv[it].x; Bs[k4*4+1][rl]=bv[it].y;
            Bs[k4*4+2][rl]=bv[it].z; Bs[k4*4+3][rl]=bv[it].w;
        }
        __syncthreads();
        #pragma unroll
        for (int k=0;k<16;k++){
            float4 a0 = *(const float4*)&As[k][tr*8];
            float4 a1 = *(const float4*)&As[k][tr*8+4];
            ull pa[8] = {bcast2(a0.x), bcast2(a0.y), bcast2(a0.z), bcast2(a0.w),
                         bcast2(a1.x), bcast2(a1.y), bcast2(a1.z), bcast2(a1.w)};
            ulonglong2 q0 = *(const ulonglong2*)&Bs[k][tc*8];
            ulonglong2 q1 = *(const ulonglong2*)&Bs[k][tc*8+4];
            ull rb[4] = {q0.x, q0.y, q1.x, q1.y};
            #pragma unroll
            for (int i=0;i<8;i++)
                #pragma unroll
                for (int p=0;p<4;p++)
                    acc[i][p] = ffma2(pa[i], rb[p], acc[i][p]);
        }
    }
    float* pp = g_part + (size_t)ks*NB*NB;
    #pragma unroll
    for (int i=0;i<8;i++)
        #pragma unroll
        for (int p=0;p<4;p++){
            float2 v = unpk2(acc[i][p]);
            pp[(tr*8+i)*NB + tc*8 + 2*p    ] = v.x;
            pp[(tr*8+i)*NB + tc*8 + 2*p + 1] = v.y;
        }
}

// ---------------- K5: deterministic split-K reduce ----------------
__global__ __launch_bounds__(256) void k5_reduce(float* __restrict__ y)
{
    int o = blockIdx.x*256 + threadIdx.x;   // 16384 outputs
    float s = 0.f;
    #pragma unroll 4
    for (int ks = 0; ks < KSPLIT; ks++)
        s += g_part[(size_t)ks*NB*NB + o];
    y[o] = s;
}

// ---------------- launcher ----------------
extern "C" void kernel_launch(void* const* d_in, const int* in_sizes, int n_in,
                              void* d_out, int out_size)
{
    const float* x    = (const float*)d_in[0];   // 128 x 16384
    const float* filt = (const float*)d_in[1];   // 4096 x 1024
    const float* w1   = (const float*)d_in[2];   // 128 x 128
    const float* w2   = (const float*)d_in[3];   // 256 x 128 x 25
    const float* beta = (const float*)d_in[4];   // 128 x 49408
    float* y = (float*)d_out;                    // 128 x 128

    static int smem_set = 0;
    if (!smem_set) {
        cudaFuncSetAttribute(k1_spec_mma, cudaFuncAttributeMaxDynamicSharedMemorySize,
                             MM_SMEM_TOTAL);
        cudaFuncSetAttribute(k3_conv2_mma, cudaFuncAttributeMaxDynamicSharedMemorySize,
                             MM_SMEM_TOTAL);
        smem_set = 1;
    }

    k0_x    <<<NB*WIN/256, 256>>>(x);
    k0_filt <<<dim3(DD/32, NF/32), 256>>>(filt);
    k0_w2b  <<<NK3, 256>>>(w2);
    k1_spec_mma<<<dim3(25, 8), 512, MM_SMEM_TOTAL>>>();
    k2_conv1<<<dim3(NB*NRG, 2), 256>>>(w1);
    k3_conv2_mma<<<dim3(KSPLIT, 2), 512, MM_SMEM_TOTAL>>>();
    k4_beta <<<KSPLIT, 256>>>(beta);
    k5_reduce<<<NB*NB/256, 256>>>(y);
}